// round 1
// baseline (speedup 1.0000x reference)
#include <cuda_runtime.h>
#include <cuda_bf16.h>
#include <math_constants.h>

// Problem constants
#define B_   2
#define T_   2048
#define D_   2048
#define H_   16
#define HKV_ 4
#define HD_  128
#define G_   (H_ / HKV_)      // 4
#define M_   (B_ * T_)        // 4096
#define KVD_ (HKV_ * HD_)     // 512

// ---------------------------------------------------------------------------
// Scratch (device globals; no allocation allowed)
// ---------------------------------------------------------------------------
__device__ float g_q[(size_t)M_ * D_];     // 32 MB: Q after proj (+RoPE in place)
__device__ float g_k[(size_t)M_ * KVD_];   //  8 MB
__device__ float g_v[(size_t)M_ * KVD_];   //  8 MB
__device__ float g_attn[(size_t)M_ * D_];  // 32 MB: attention output [b*T+t][h*HD+d]

// ---------------------------------------------------------------------------
// GEMM: C[M,N] = A[M,K] @ B[N,K]^T   (row-major A, row-major B with N rows)
// BM=BN=128, BK=16, 256 threads, 8x8 microtile
// ---------------------------------------------------------------------------
__global__ __launch_bounds__(256) void gemm_nt_kernel(
    const float* __restrict__ A, const float* __restrict__ Bm,
    float* __restrict__ C, int M, int N, int K)
{
    __shared__ float As[16][128];
    __shared__ float Bs[16][128];

    const int tid  = threadIdx.x;
    const int row0 = blockIdx.y * 128;
    const int col0 = blockIdx.x * 128;
    const int trow = (tid >> 4) * 8;   // 0..120
    const int tcol = (tid & 15) * 8;   // 0..120

    float acc[8][8];
#pragma unroll
    for (int i = 0; i < 8; i++)
#pragma unroll
        for (int j = 0; j < 8; j++) acc[i][j] = 0.f;

    for (int k0 = 0; k0 < K; k0 += 16) {
        // load A tile (128x16) and B tile (128x16), store k-major in smem
#pragma unroll
        for (int i = 0; i < 2; i++) {
            int v  = tid + i * 256;        // 0..511
            int m  = v >> 2;               // 0..127
            int kq = (v & 3) << 2;         // 0,4,8,12
            float4 a = *(const float4*)&A[(size_t)(row0 + m) * K + k0 + kq];
            As[kq + 0][m] = a.x; As[kq + 1][m] = a.y;
            As[kq + 2][m] = a.z; As[kq + 3][m] = a.w;
            float4 b = *(const float4*)&Bm[(size_t)(col0 + m) * K + k0 + kq];
            Bs[kq + 0][m] = b.x; Bs[kq + 1][m] = b.y;
            Bs[kq + 2][m] = b.z; Bs[kq + 3][m] = b.w;
        }
        __syncthreads();

#pragma unroll
        for (int kk = 0; kk < 16; kk++) {
            float4 a0 = *(const float4*)&As[kk][trow];
            float4 a1 = *(const float4*)&As[kk][trow + 4];
            float4 b0 = *(const float4*)&Bs[kk][tcol];
            float4 b1 = *(const float4*)&Bs[kk][tcol + 4];
            float ar[8] = {a0.x, a0.y, a0.z, a0.w, a1.x, a1.y, a1.z, a1.w};
            float br[8] = {b0.x, b0.y, b0.z, b0.w, b1.x, b1.y, b1.z, b1.w};
#pragma unroll
            for (int i = 0; i < 8; i++)
#pragma unroll
                for (int j = 0; j < 8; j++)
                    acc[i][j] = fmaf(ar[i], br[j], acc[i][j]);
        }
        __syncthreads();
    }

#pragma unroll
    for (int i = 0; i < 8; i++) {
        float4 c0 = {acc[i][0], acc[i][1], acc[i][2], acc[i][3]};
        float4 c1 = {acc[i][4], acc[i][5], acc[i][6], acc[i][7]};
        size_t base = (size_t)(row0 + trow + i) * N + col0 + tcol;
        *(float4*)&C[base]     = c0;
        *(float4*)&C[base + 4] = c1;
    }
}

// ---------------------------------------------------------------------------
// RoPE: in-place on Q [M, H*HD] and K [M, HKV*HD]
// out[i]    = x[i]*cos[i]       - x[i+64]*sin[i]
// out[i+64] = x[i+64]*cos[i+64] + x[i]*sin[i+64]
// ---------------------------------------------------------------------------
__global__ __launch_bounds__(256) void rope_kernel(
    float* __restrict__ q, float* __restrict__ k,
    const float* __restrict__ cosT, const float* __restrict__ sinT)
{
    const int bt  = blockIdx.x;          // 0..M_-1
    const int t   = bt & (T_ - 1);
    const int tid = threadIdx.x;
    const float* cr = cosT + (size_t)t * HD_;
    const float* sr = sinT + (size_t)t * HD_;

    float* qrow = q + (size_t)bt * D_;
    for (int p = tid; p < H_ * 64; p += 256) {
        int h = p >> 6, i = p & 63;
        float* base = qrow + h * HD_;
        float q1 = base[i], q2 = base[i + 64];
        base[i]      = q1 * cr[i]      - q2 * sr[i];
        base[i + 64] = q2 * cr[i + 64] + q1 * sr[i + 64];
    }
    float* krow = k + (size_t)bt * KVD_;
    for (int p = tid; p < HKV_ * 64; p += 256) {
        int h = p >> 6, i = p & 63;
        float* base = krow + h * HD_;
        float k1 = base[i], k2 = base[i + 64];
        base[i]      = k1 * cr[i]      - k2 * sr[i];
        base[i + 64] = k2 * cr[i + 64] + k1 * sr[i + 64];
    }
}

// ---------------------------------------------------------------------------
// Causal flash attention, fp32.
// Grid: (T/64, H, B). Block: 256 threads (tx in [0,16), ty in [0,16)).
// Tiles: BQ=64 queries x BK=64 keys, HD=128.
// Smem: Qs[128][64] k-major, Ks[128][64] k-major, Vs[64][128] row-major.
// P (64x64, stride 65) aliases the Ks region between syncs.
// ---------------------------------------------------------------------------
#define ATTN_SMEM_FLOATS (8192 * 3)

__global__ __launch_bounds__(256) void attn_kernel(
    const float* __restrict__ q, const float* __restrict__ k,
    const float* __restrict__ v, float* __restrict__ o)
{
    extern __shared__ float sm[];
    float* Qs = sm;            // [128][64]
    float* Ks = sm + 8192;     // [128][64]
    float* Vs = sm + 16384;    // [64][128]
    float* Ps = Ks;            // alias, stride 65 (4160 <= 8192)

    const int qt  = blockIdx.x;
    const int h   = blockIdx.y;
    const int b   = blockIdx.z;
    const int kvh = h >> 2;               // h / G_
    const int q0  = qt * 64;
    const int tid = threadIdx.x;
    const int tx  = tid & 15;
    const int ty  = tid >> 4;
    const float scale = 0.08838834764831845f;   // 1/sqrt(128)

    // Load Q tile (scaled), k-major
    {
        int r  = tid >> 2;                 // 0..63
        int d0 = (tid & 3) * 32;
        const float* src = q + (size_t)(b * T_ + q0 + r) * D_ + h * HD_ + d0;
#pragma unroll
        for (int j = 0; j < 32; j += 4) {
            float4 a = *(const float4*)(src + j);
            Qs[(d0 + j + 0) * 64 + r] = a.x * scale;
            Qs[(d0 + j + 1) * 64 + r] = a.y * scale;
            Qs[(d0 + j + 2) * 64 + r] = a.z * scale;
            Qs[(d0 + j + 3) * 64 + r] = a.w * scale;
        }
    }

    float m_i[4], l_i[4], O[4][8];
#pragma unroll
    for (int i = 0; i < 4; i++) {
        m_i[i] = -CUDART_INF_F; l_i[i] = 0.f;
#pragma unroll
        for (int c = 0; c < 8; c++) O[i][c] = 0.f;
    }

    for (int kt = 0; kt <= qt; kt++) {
        const int k0 = kt * 64;
        // Load K (k-major) and V (row-major)
        {
            int n  = tid >> 2;
            int d0 = (tid & 3) * 32;
            const float* src = k + (size_t)(b * T_ + k0 + n) * KVD_ + kvh * HD_ + d0;
#pragma unroll
            for (int j = 0; j < 32; j += 4) {
                float4 a = *(const float4*)(src + j);
                Ks[(d0 + j + 0) * 64 + n] = a.x;
                Ks[(d0 + j + 1) * 64 + n] = a.y;
                Ks[(d0 + j + 2) * 64 + n] = a.z;
                Ks[(d0 + j + 3) * 64 + n] = a.w;
            }
#pragma unroll
            for (int i = 0; i < 8; i++) {
                int idx = tid + i * 256;        // 0..2047
                int nn  = idx >> 5;             // 0..63
                int d4  = (idx & 31) << 2;      // 0..124
                *(float4*)&Vs[nn * 128 + d4] =
                    *(const float4*)(v + (size_t)(b * T_ + k0 + nn) * KVD_ + kvh * HD_ + d4);
            }
        }
        __syncthreads();

        // S = Q K^T (4x4 per thread)
        float s[4][4];
#pragma unroll
        for (int i = 0; i < 4; i++)
#pragma unroll
            for (int j = 0; j < 4; j++) s[i][j] = 0.f;

#pragma unroll 8
        for (int d = 0; d < 128; d++) {
            float4 aa = *(const float4*)&Qs[d * 64 + ty * 4];
            float4 bb = *(const float4*)&Ks[d * 64 + tx * 4];
            float ar[4] = {aa.x, aa.y, aa.z, aa.w};
            float br[4] = {bb.x, bb.y, bb.z, bb.w};
#pragma unroll
            for (int i = 0; i < 4; i++)
#pragma unroll
                for (int j = 0; j < 4; j++)
                    s[i][j] = fmaf(ar[i], br[j], s[i][j]);
        }

        if (kt == qt) {   // causal mask on diagonal tile
#pragma unroll
            for (int i = 0; i < 4; i++)
#pragma unroll
                for (int j = 0; j < 4; j++)
                    if (k0 + tx * 4 + j > q0 + ty * 4 + i) s[i][j] = -CUDART_INF_F;
        }

        // online softmax stats (row = ty*4+i, reduce across tx half-warp)
        float mt[4], al[4], rs[4];
#pragma unroll
        for (int i = 0; i < 4; i++) {
            mt[i] = fmaxf(fmaxf(s[i][0], s[i][1]), fmaxf(s[i][2], s[i][3]));
#pragma unroll
            for (int off = 8; off > 0; off >>= 1)
                mt[i] = fmaxf(mt[i], __shfl_xor_sync(0xffffffffu, mt[i], off));
            float mn = fmaxf(m_i[i], mt[i]);
            al[i] = __expf(m_i[i] - mn);
            m_i[i] = mn;
            float sum = 0.f;
#pragma unroll
            for (int j = 0; j < 4; j++) {
                s[i][j] = __expf(s[i][j] - mn);
                sum += s[i][j];
            }
#pragma unroll
            for (int off = 8; off > 0; off >>= 1)
                sum += __shfl_xor_sync(0xffffffffu, sum, off);
            rs[i] = sum;
            l_i[i] = l_i[i] * al[i] + rs[i];
#pragma unroll
            for (int c = 0; c < 8; c++) O[i][c] *= al[i];
        }

        __syncthreads();   // everyone done reading Ks before P overwrite
        // store P transposed: Ps[col][row], stride 65
#pragma unroll
        for (int j = 0; j < 4; j++)
#pragma unroll
            for (int i = 0; i < 4; i++)
                Ps[(tx * 4 + j) * 65 + ty * 4 + i] = s[i][j];
        __syncthreads();

        // O += P @ V
#pragma unroll 4
        for (int n = 0; n < 64; n++) {
            float a0 = Ps[n * 65 + ty * 4 + 0];
            float a1 = Ps[n * 65 + ty * 4 + 1];
            float a2 = Ps[n * 65 + ty * 4 + 2];
            float a3 = Ps[n * 65 + ty * 4 + 3];
            float4 b0 = *(const float4*)&Vs[n * 128 + tx * 8];
            float4 b1 = *(const float4*)&Vs[n * 128 + tx * 8 + 4];
            float br[8] = {b0.x, b0.y, b0.z, b0.w, b1.x, b1.y, b1.z, b1.w};
#pragma unroll
            for (int c = 0; c < 8; c++) {
                O[0][c] = fmaf(a0, br[c], O[0][c]);
                O[1][c] = fmaf(a1, br[c], O[1][c]);
                O[2][c] = fmaf(a2, br[c], O[2][c]);
                O[3][c] = fmaf(a3, br[c], O[3][c]);
            }
        }
        __syncthreads();
    }

    // epilogue: normalize and store to [b*T+t][h*HD+d]
#pragma unroll
    for (int i = 0; i < 4; i++) {
        float inv = 1.0f / l_i[i];
        float4 c0 = {O[i][0] * inv, O[i][1] * inv, O[i][2] * inv, O[i][3] * inv};
        float4 c1 = {O[i][4] * inv, O[i][5] * inv, O[i][6] * inv, O[i][7] * inv};
        size_t base = (size_t)(b * T_ + q0 + ty * 4 + i) * D_ + h * HD_ + tx * 8;
        *(float4*)&o[base]     = c0;
        *(float4*)&o[base + 4] = c1;
    }
}

// ---------------------------------------------------------------------------
// Launcher
// ---------------------------------------------------------------------------
extern "C" void kernel_launch(void* const* d_in, const int* in_sizes, int n_in,
                              void* d_out, int out_size)
{
    const float* x    = (const float*)d_in[0];
    const float* cosT = (const float*)d_in[1];
    const float* sinT = (const float*)d_in[2];
    const float* Wq   = (const float*)d_in[3];
    const float* Wk   = (const float*)d_in[4];
    const float* Wv   = (const float*)d_in[5];
    const float* Wo   = (const float*)d_in[6];
    float* out = (float*)d_out;

    float *gq, *gk, *gv, *gattn;
    cudaGetSymbolAddress((void**)&gq,    g_q);
    cudaGetSymbolAddress((void**)&gk,    g_k);
    cudaGetSymbolAddress((void**)&gv,    g_v);
    cudaGetSymbolAddress((void**)&gattn, g_attn);

    const int smem_attn = ATTN_SMEM_FLOATS * (int)sizeof(float);   // 96 KB
    cudaFuncSetAttribute(attn_kernel, cudaFuncAttributeMaxDynamicSharedMemorySize,
                         smem_attn);

    dim3 blk(256);
    dim3 gq_grid(D_ / 128, M_ / 128);
    dim3 gkv_grid(KVD_ / 128, M_ / 128);

    gemm_nt_kernel<<<gq_grid,  blk>>>(x, Wq, gq, M_, D_,   D_);
    gemm_nt_kernel<<<gkv_grid, blk>>>(x, Wk, gk, M_, KVD_, D_);
    gemm_nt_kernel<<<gkv_grid, blk>>>(x, Wv, gv, M_, KVD_, D_);

    rope_kernel<<<M_, blk>>>(gq, gk, cosT, sinT);

    dim3 ga(T_ / 64, H_, B_);
    attn_kernel<<<ga, blk, smem_attn>>>(gq, gk, gv, gattn);

    gemm_nt_kernel<<<gq_grid, blk>>>(gattn, Wo, out, M_, D_, D_);
}

// round 2
// speedup vs baseline: 1.4138x; 1.4138x over previous
#include <cuda_runtime.h>
#include <cuda_bf16.h>
#include <math_constants.h>
#include <stdint.h>

// Problem constants
#define B_   2
#define T_   2048
#define D_   2048
#define H_   16
#define HKV_ 4
#define HD_  128
#define G_   (H_ / HKV_)      // 4
#define M_   (B_ * T_)        // 4096
#define KVD_ (HKV_ * HD_)     // 512

// ---------------------------------------------------------------------------
// Scratch (device globals; no allocation allowed)
// ---------------------------------------------------------------------------
__device__ float g_q[(size_t)M_ * D_];     // 32 MB
__device__ float g_k[(size_t)M_ * KVD_];   //  8 MB
__device__ float g_v[(size_t)M_ * KVD_];   //  8 MB
__device__ float g_attn[(size_t)M_ * D_];  // 32 MB

// ---------------------------------------------------------------------------
// tf32 helpers
// ---------------------------------------------------------------------------
__device__ __forceinline__ uint32_t f2tf32(float x) {
    uint32_t r;
    asm("cvt.rna.tf32.f32 %0, %1;" : "=r"(r) : "f"(x));
    return r;
}

#define MMA_TF32(c, a, b)                                                     \
    asm volatile(                                                             \
        "mma.sync.aligned.m16n8k8.row.col.f32.tf32.tf32.f32 "                 \
        "{%0,%1,%2,%3},{%4,%5,%6,%7},{%8,%9},{%0,%1,%2,%3};"                  \
        : "+f"((c)[0]), "+f"((c)[1]), "+f"((c)[2]), "+f"((c)[3])              \
        : "r"((a)[0]), "r"((a)[1]), "r"((a)[2]), "r"((a)[3]),                 \
          "r"((b)[0]), "r"((b)[1]))

// ---------------------------------------------------------------------------
// tf32 tensor-core GEMM: C[M,N] = A[M,K] @ Bm[N,K]^T
// BM=BN=128, BK=32, 256 threads (8 warps, 2x4), warp tile 64x32.
// Smem [m][k] stride 36 (conflict-free LDS frags + STS.128 + coalesced LDG).
// Double-buffered, register prefetch, cvt.rna.tf32 on the STS path.
// ---------------------------------------------------------------------------
#define TSTRIDE 36
#define TILE_WORDS (128 * TSTRIDE)   // 4608 words = 18432 B per buffer
#define GEMM_SMEM_BYTES (4 * TILE_WORDS * 4)   // 73728 B

__global__ __launch_bounds__(256) void gemm_nt_tf32_kernel(
    const float* __restrict__ A, const float* __restrict__ Bm,
    float* __restrict__ C, int M, int N, int K)
{
    extern __shared__ uint32_t smw[];
    uint32_t* As[2] = { smw,                 smw + TILE_WORDS };
    uint32_t* Bs[2] = { smw + 2 * TILE_WORDS, smw + 3 * TILE_WORDS };

    const int tid  = threadIdx.x;
    const int lane = tid & 31;
    const int warp = tid >> 5;
    const int row0 = blockIdx.y * 128;
    const int col0 = blockIdx.x * 128;
    const int wm   = (warp >> 2) * 64;   // 0 / 64
    const int wn   = (warp & 3) * 32;    // 0..96
    const int lk   = lane & 3;
    const int lr   = lane >> 2;

    // per-thread global-load coordinates: idx -> (m = idx>>3, kq = (idx&7)*4)
    int mL[4], kqL[4];
#pragma unroll
    for (int t = 0; t < 4; t++) {
        int idx = tid + 256 * t;
        mL[t]  = idx >> 3;
        kqL[t] = (idx & 7) << 2;
    }

    float c[4][4][4];
#pragma unroll
    for (int mi = 0; mi < 4; mi++)
#pragma unroll
        for (int ni = 0; ni < 4; ni++)
#pragma unroll
            for (int r = 0; r < 4; r++) c[mi][ni][r] = 0.f;

    const int niter = K >> 5;
    float4 pa[4], pb[4];

    // prologue: tile 0 -> regs -> smem buf 0
#pragma unroll
    for (int t = 0; t < 4; t++) {
        pa[t] = *(const float4*)&A [(size_t)(row0 + mL[t]) * K + kqL[t]];
        pb[t] = *(const float4*)&Bm[(size_t)(col0 + mL[t]) * K + kqL[t]];
    }
#pragma unroll
    for (int t = 0; t < 4; t++) {
        uint4 wa = { f2tf32(pa[t].x), f2tf32(pa[t].y), f2tf32(pa[t].z), f2tf32(pa[t].w) };
        *(uint4*)&As[0][mL[t] * TSTRIDE + kqL[t]] = wa;
        uint4 wb = { f2tf32(pb[t].x), f2tf32(pb[t].y), f2tf32(pb[t].z), f2tf32(pb[t].w) };
        *(uint4*)&Bs[0][mL[t] * TSTRIDE + kqL[t]] = wb;
    }
    __syncthreads();

    for (int it = 0; it < niter; ++it) {
        const int cur = it & 1;
        if (it + 1 < niter) {
            const int k0 = (it + 1) << 5;
#pragma unroll
            for (int t = 0; t < 4; t++) {
                pa[t] = *(const float4*)&A [(size_t)(row0 + mL[t]) * K + k0 + kqL[t]];
                pb[t] = *(const float4*)&Bm[(size_t)(col0 + mL[t]) * K + k0 + kqL[t]];
            }
        }

        const uint32_t* __restrict__ as = As[cur];
        const uint32_t* __restrict__ bs = Bs[cur];
#pragma unroll
        for (int kc = 0; kc < 32; kc += 8) {
            uint32_t af[4][4], bf[4][2];
#pragma unroll
            for (int mi = 0; mi < 4; mi++) {
                int m = wm + 16 * mi;
                af[mi][0] = as[(m + lr)     * TSTRIDE + kc + lk];
                af[mi][1] = as[(m + lr + 8) * TSTRIDE + kc + lk];
                af[mi][2] = as[(m + lr)     * TSTRIDE + kc + lk + 4];
                af[mi][3] = as[(m + lr + 8) * TSTRIDE + kc + lk + 4];
            }
#pragma unroll
            for (int ni = 0; ni < 4; ni++) {
                int n = wn + 8 * ni;
                bf[ni][0] = bs[(n + lr) * TSTRIDE + kc + lk];
                bf[ni][1] = bs[(n + lr) * TSTRIDE + kc + lk + 4];
            }
#pragma unroll
            for (int mi = 0; mi < 4; mi++)
#pragma unroll
                for (int ni = 0; ni < 4; ni++)
                    MMA_TF32(c[mi][ni], af[mi], bf[ni]);
        }

        if (it + 1 < niter) {
            const int nb = (it + 1) & 1;
#pragma unroll
            for (int t = 0; t < 4; t++) {
                uint4 wa = { f2tf32(pa[t].x), f2tf32(pa[t].y), f2tf32(pa[t].z), f2tf32(pa[t].w) };
                *(uint4*)&As[nb][mL[t] * TSTRIDE + kqL[t]] = wa;
                uint4 wb = { f2tf32(pb[t].x), f2tf32(pb[t].y), f2tf32(pb[t].z), f2tf32(pb[t].w) };
                *(uint4*)&Bs[nb][mL[t] * TSTRIDE + kqL[t]] = wb;
            }
        }
        __syncthreads();
    }

    // epilogue
#pragma unroll
    for (int mi = 0; mi < 4; mi++) {
#pragma unroll
        for (int ni = 0; ni < 4; ni++) {
            int r  = row0 + wm + 16 * mi + lr;
            int cc = col0 + wn + 8 * ni + 2 * lk;
            C[(size_t)r * N + cc]           = c[mi][ni][0];
            C[(size_t)r * N + cc + 1]       = c[mi][ni][1];
            C[(size_t)(r + 8) * N + cc]     = c[mi][ni][2];
            C[(size_t)(r + 8) * N + cc + 1] = c[mi][ni][3];
        }
    }
}

// ---------------------------------------------------------------------------
// RoPE: in-place on Q [M, H*HD] and K [M, HKV*HD]
// ---------------------------------------------------------------------------
__global__ __launch_bounds__(256) void rope_kernel(
    float* __restrict__ q, float* __restrict__ k,
    const float* __restrict__ cosT, const float* __restrict__ sinT)
{
    const int bt  = blockIdx.x;
    const int t   = bt & (T_ - 1);
    const int tid = threadIdx.x;
    const float* cr = cosT + (size_t)t * HD_;
    const float* sr = sinT + (size_t)t * HD_;

    float* qrow = q + (size_t)bt * D_;
    for (int p = tid; p < H_ * 64; p += 256) {
        int h = p >> 6, i = p & 63;
        float* base = qrow + h * HD_;
        float q1 = base[i], q2 = base[i + 64];
        base[i]      = q1 * cr[i]      - q2 * sr[i];
        base[i + 64] = q2 * cr[i + 64] + q1 * sr[i + 64];
    }
    float* krow = k + (size_t)bt * KVD_;
    for (int p = tid; p < HKV_ * 64; p += 256) {
        int h = p >> 6, i = p & 63;
        float* base = krow + h * HD_;
        float k1 = base[i], k2 = base[i + 64];
        base[i]      = k1 * cr[i]      - k2 * sr[i];
        base[i + 64] = k2 * cr[i + 64] + k1 * sr[i + 64];
    }
}

// ---------------------------------------------------------------------------
// Causal flash attention, fp32 SIMT (unchanged from R1).
// ---------------------------------------------------------------------------
#define ATTN_SMEM_FLOATS (8192 * 3)

__global__ __launch_bounds__(256) void attn_kernel(
    const float* __restrict__ q, const float* __restrict__ k,
    const float* __restrict__ v, float* __restrict__ o)
{
    extern __shared__ float sm[];
    float* Qs = sm;            // [128][64]
    float* Ks = sm + 8192;     // [128][64]
    float* Vs = sm + 16384;    // [64][128]
    float* Ps = Ks;            // alias, stride 65

    const int qt  = blockIdx.x;
    const int h   = blockIdx.y;
    const int b   = blockIdx.z;
    const int kvh = h >> 2;
    const int q0  = qt * 64;
    const int tid = threadIdx.x;
    const int tx  = tid & 15;
    const int ty  = tid >> 4;
    const float scale = 0.08838834764831845f;   // 1/sqrt(128)

    {
        int r  = tid >> 2;
        int d0 = (tid & 3) * 32;
        const float* src = q + (size_t)(b * T_ + q0 + r) * D_ + h * HD_ + d0;
#pragma unroll
        for (int j = 0; j < 32; j += 4) {
            float4 a = *(const float4*)(src + j);
            Qs[(d0 + j + 0) * 64 + r] = a.x * scale;
            Qs[(d0 + j + 1) * 64 + r] = a.y * scale;
            Qs[(d0 + j + 2) * 64 + r] = a.z * scale;
            Qs[(d0 + j + 3) * 64 + r] = a.w * scale;
        }
    }

    float m_i[4], l_i[4], O[4][8];
#pragma unroll
    for (int i = 0; i < 4; i++) {
        m_i[i] = -CUDART_INF_F; l_i[i] = 0.f;
#pragma unroll
        for (int c = 0; c < 8; c++) O[i][c] = 0.f;
    }

    for (int kt = 0; kt <= qt; kt++) {
        const int k0 = kt * 64;
        {
            int n  = tid >> 2;
            int d0 = (tid & 3) * 32;
            const float* src = k + (size_t)(b * T_ + k0 + n) * KVD_ + kvh * HD_ + d0;
#pragma unroll
            for (int j = 0; j < 32; j += 4) {
                float4 a = *(const float4*)(src + j);
                Ks[(d0 + j + 0) * 64 + n] = a.x;
                Ks[(d0 + j + 1) * 64 + n] = a.y;
                Ks[(d0 + j + 2) * 64 + n] = a.z;
                Ks[(d0 + j + 3) * 64 + n] = a.w;
            }
#pragma unroll
            for (int i = 0; i < 8; i++) {
                int idx = tid + i * 256;
                int nn  = idx >> 5;
                int d4  = (idx & 31) << 2;
                *(float4*)&Vs[nn * 128 + d4] =
                    *(const float4*)(v + (size_t)(b * T_ + k0 + nn) * KVD_ + kvh * HD_ + d4);
            }
        }
        __syncthreads();

        float s[4][4];
#pragma unroll
        for (int i = 0; i < 4; i++)
#pragma unroll
            for (int j = 0; j < 4; j++) s[i][j] = 0.f;

#pragma unroll 8
        for (int d = 0; d < 128; d++) {
            float4 aa = *(const float4*)&Qs[d * 64 + ty * 4];
            float4 bb = *(const float4*)&Ks[d * 64 + tx * 4];
            float ar[4] = {aa.x, aa.y, aa.z, aa.w};
            float br[4] = {bb.x, bb.y, bb.z, bb.w};
#pragma unroll
            for (int i = 0; i < 4; i++)
#pragma unroll
                for (int j = 0; j < 4; j++)
                    s[i][j] = fmaf(ar[i], br[j], s[i][j]);
        }

        if (kt == qt) {
#pragma unroll
            for (int i = 0; i < 4; i++)
#pragma unroll
                for (int j = 0; j < 4; j++)
                    if (k0 + tx * 4 + j > q0 + ty * 4 + i) s[i][j] = -CUDART_INF_F;
        }

        float mt[4], al[4], rs[4];
#pragma unroll
        for (int i = 0; i < 4; i++) {
            mt[i] = fmaxf(fmaxf(s[i][0], s[i][1]), fmaxf(s[i][2], s[i][3]));
#pragma unroll
            for (int off = 8; off > 0; off >>= 1)
                mt[i] = fmaxf(mt[i], __shfl_xor_sync(0xffffffffu, mt[i], off));
            float mn = fmaxf(m_i[i], mt[i]);
            al[i] = __expf(m_i[i] - mn);
            m_i[i] = mn;
            float sum = 0.f;
#pragma unroll
            for (int j = 0; j < 4; j++) {
                s[i][j] = __expf(s[i][j] - mn);
                sum += s[i][j];
            }
#pragma unroll
            for (int off = 8; off > 0; off >>= 1)
                sum += __shfl_xor_sync(0xffffffffu, sum, off);
            rs[i] = sum;
            l_i[i] = l_i[i] * al[i] + rs[i];
#pragma unroll
            for (int c = 0; c < 8; c++) O[i][c] *= al[i];
        }

        __syncthreads();
#pragma unroll
        for (int j = 0; j < 4; j++)
#pragma unroll
            for (int i = 0; i < 4; i++)
                Ps[(tx * 4 + j) * 65 + ty * 4 + i] = s[i][j];
        __syncthreads();

#pragma unroll 4
        for (int n = 0; n < 64; n++) {
            float a0 = Ps[n * 65 + ty * 4 + 0];
            float a1 = Ps[n * 65 + ty * 4 + 1];
            float a2 = Ps[n * 65 + ty * 4 + 2];
            float a3 = Ps[n * 65 + ty * 4 + 3];
            float4 b0 = *(const float4*)&Vs[n * 128 + tx * 8];
            float4 b1 = *(const float4*)&Vs[n * 128 + tx * 8 + 4];
            float br[8] = {b0.x, b0.y, b0.z, b0.w, b1.x, b1.y, b1.z, b1.w};
#pragma unroll
            for (int c = 0; c < 8; c++) {
                O[0][c] = fmaf(a0, br[c], O[0][c]);
                O[1][c] = fmaf(a1, br[c], O[1][c]);
                O[2][c] = fmaf(a2, br[c], O[2][c]);
                O[3][c] = fmaf(a3, br[c], O[3][c]);
            }
        }
        __syncthreads();
    }

#pragma unroll
    for (int i = 0; i < 4; i++) {
        float inv = 1.0f / l_i[i];
        float4 c0 = {O[i][0] * inv, O[i][1] * inv, O[i][2] * inv, O[i][3] * inv};
        float4 c1 = {O[i][4] * inv, O[i][5] * inv, O[i][6] * inv, O[i][7] * inv};
        size_t base = (size_t)(b * T_ + q0 + ty * 4 + i) * D_ + h * HD_ + tx * 8;
        *(float4*)&o[base]     = c0;
        *(float4*)&o[base + 4] = c1;
    }
}

// ---------------------------------------------------------------------------
// Launcher
// ---------------------------------------------------------------------------
extern "C" void kernel_launch(void* const* d_in, const int* in_sizes, int n_in,
                              void* d_out, int out_size)
{
    const float* x    = (const float*)d_in[0];
    const float* cosT = (const float*)d_in[1];
    const float* sinT = (const float*)d_in[2];
    const float* Wq   = (const float*)d_in[3];
    const float* Wk   = (const float*)d_in[4];
    const float* Wv   = (const float*)d_in[5];
    const float* Wo   = (const float*)d_in[6];
    float* out = (float*)d_out;

    float *gq, *gk, *gv, *gattn;
    cudaGetSymbolAddress((void**)&gq,    g_q);
    cudaGetSymbolAddress((void**)&gk,    g_k);
    cudaGetSymbolAddress((void**)&gv,    g_v);
    cudaGetSymbolAddress((void**)&gattn, g_attn);

    const int smem_attn = ATTN_SMEM_FLOATS * (int)sizeof(float);   // 96 KB
    cudaFuncSetAttribute(attn_kernel, cudaFuncAttributeMaxDynamicSharedMemorySize,
                         smem_attn);
    cudaFuncSetAttribute(gemm_nt_tf32_kernel,
                         cudaFuncAttributeMaxDynamicSharedMemorySize,
                         GEMM_SMEM_BYTES);

    dim3 blk(256);
    dim3 gq_grid(D_ / 128, M_ / 128);
    dim3 gkv_grid(KVD_ / 128, M_ / 128);

    gemm_nt_tf32_kernel<<<gq_grid,  blk, GEMM_SMEM_BYTES>>>(x, Wq, gq, M_, D_,   D_);
    gemm_nt_tf32_kernel<<<gkv_grid, blk, GEMM_SMEM_BYTES>>>(x, Wk, gk, M_, KVD_, D_);
    gemm_nt_tf32_kernel<<<gkv_grid, blk, GEMM_SMEM_BYTES>>>(x, Wv, gv, M_, KVD_, D_);

    rope_kernel<<<M_, blk>>>(gq, gk, cosT, sinT);

    dim3 ga(T_ / 64, H_, B_);
    attn_kernel<<<ga, blk, smem_attn>>>(gq, gk, gv, gattn);

    gemm_nt_tf32_kernel<<<gq_grid, blk, GEMM_SMEM_BYTES>>>(gattn, Wo, out, M_, D_, D_);
}

// round 3
// speedup vs baseline: 2.2009x; 1.5567x over previous
#include <cuda_runtime.h>
#include <cuda_bf16.h>
#include <math_constants.h>
#include <stdint.h>

// Problem constants
#define B_   2
#define T_   2048
#define D_   2048
#define H_   16
#define HKV_ 4
#define HD_  128
#define G_   (H_ / HKV_)      // 4
#define M_   (B_ * T_)        // 4096
#define KVD_ (HKV_ * HD_)     // 512

// ---------------------------------------------------------------------------
// Scratch (device globals; no allocation allowed)
// ---------------------------------------------------------------------------
__device__ float g_q[(size_t)M_ * D_];     // 32 MB
__device__ float g_k[(size_t)M_ * KVD_];   //  8 MB
__device__ float g_v[(size_t)M_ * KVD_];   //  8 MB
__device__ float g_attn[(size_t)M_ * D_];  // 32 MB

// ---------------------------------------------------------------------------
// tf32 helpers
// ---------------------------------------------------------------------------
__device__ __forceinline__ uint32_t f2tf32(float x) {
    uint32_t r;
    asm("cvt.rna.tf32.f32 %0, %1;" : "=r"(r) : "f"(x));
    return r;
}

#define MMA_TF32(c, a, b)                                                     \
    asm volatile(                                                             \
        "mma.sync.aligned.m16n8k8.row.col.f32.tf32.tf32.f32 "                 \
        "{%0,%1,%2,%3},{%4,%5,%6,%7},{%8,%9},{%0,%1,%2,%3};"                  \
        : "+f"((c)[0]), "+f"((c)[1]), "+f"((c)[2]), "+f"((c)[3])              \
        : "r"((a)[0]), "r"((a)[1]), "r"((a)[2]), "r"((a)[3]),                 \
          "r"((b)[0]), "r"((b)[1]))

// ---------------------------------------------------------------------------
// tf32 tensor-core GEMM: C[M,N] = A[M,K] @ Bm[N,K]^T   (unchanged from R2)
// ---------------------------------------------------------------------------
#define TSTRIDE 36
#define TILE_WORDS (128 * TSTRIDE)
#define GEMM_SMEM_BYTES (4 * TILE_WORDS * 4)   // 73728 B

__global__ __launch_bounds__(256) void gemm_nt_tf32_kernel(
    const float* __restrict__ A, const float* __restrict__ Bm,
    float* __restrict__ C, int M, int N, int K)
{
    extern __shared__ uint32_t smw[];
    uint32_t* As[2] = { smw,                  smw + TILE_WORDS };
    uint32_t* Bs[2] = { smw + 2 * TILE_WORDS, smw + 3 * TILE_WORDS };

    const int tid  = threadIdx.x;
    const int lane = tid & 31;
    const int warp = tid >> 5;
    const int row0 = blockIdx.y * 128;
    const int col0 = blockIdx.x * 128;
    const int wm   = (warp >> 2) * 64;
    const int wn   = (warp & 3) * 32;
    const int lk   = lane & 3;
    const int lr   = lane >> 2;

    int mL[4], kqL[4];
#pragma unroll
    for (int t = 0; t < 4; t++) {
        int idx = tid + 256 * t;
        mL[t]  = idx >> 3;
        kqL[t] = (idx & 7) << 2;
    }

    float c[4][4][4];
#pragma unroll
    for (int mi = 0; mi < 4; mi++)
#pragma unroll
        for (int ni = 0; ni < 4; ni++)
#pragma unroll
            for (int r = 0; r < 4; r++) c[mi][ni][r] = 0.f;

    const int niter = K >> 5;
    float4 pa[4], pb[4];

#pragma unroll
    for (int t = 0; t < 4; t++) {
        pa[t] = *(const float4*)&A [(size_t)(row0 + mL[t]) * K + kqL[t]];
        pb[t] = *(const float4*)&Bm[(size_t)(col0 + mL[t]) * K + kqL[t]];
    }
#pragma unroll
    for (int t = 0; t < 4; t++) {
        uint4 wa = { f2tf32(pa[t].x), f2tf32(pa[t].y), f2tf32(pa[t].z), f2tf32(pa[t].w) };
        *(uint4*)&As[0][mL[t] * TSTRIDE + kqL[t]] = wa;
        uint4 wb = { f2tf32(pb[t].x), f2tf32(pb[t].y), f2tf32(pb[t].z), f2tf32(pb[t].w) };
        *(uint4*)&Bs[0][mL[t] * TSTRIDE + kqL[t]] = wb;
    }
    __syncthreads();

    for (int it = 0; it < niter; ++it) {
        const int cur = it & 1;
        if (it + 1 < niter) {
            const int k0 = (it + 1) << 5;
#pragma unroll
            for (int t = 0; t < 4; t++) {
                pa[t] = *(const float4*)&A [(size_t)(row0 + mL[t]) * K + k0 + kqL[t]];
                pb[t] = *(const float4*)&Bm[(size_t)(col0 + mL[t]) * K + k0 + kqL[t]];
            }
        }

        const uint32_t* __restrict__ as = As[cur];
        const uint32_t* __restrict__ bs = Bs[cur];
#pragma unroll
        for (int kc = 0; kc < 32; kc += 8) {
            uint32_t af[4][4], bf[4][2];
#pragma unroll
            for (int mi = 0; mi < 4; mi++) {
                int m = wm + 16 * mi;
                af[mi][0] = as[(m + lr)     * TSTRIDE + kc + lk];
                af[mi][1] = as[(m + lr + 8) * TSTRIDE + kc + lk];
                af[mi][2] = as[(m + lr)     * TSTRIDE + kc + lk + 4];
                af[mi][3] = as[(m + lr + 8) * TSTRIDE + kc + lk + 4];
            }
#pragma unroll
            for (int ni = 0; ni < 4; ni++) {
                int n = wn + 8 * ni;
                bf[ni][0] = bs[(n + lr) * TSTRIDE + kc + lk];
                bf[ni][1] = bs[(n + lr) * TSTRIDE + kc + lk + 4];
            }
#pragma unroll
            for (int mi = 0; mi < 4; mi++)
#pragma unroll
                for (int ni = 0; ni < 4; ni++)
                    MMA_TF32(c[mi][ni], af[mi], bf[ni]);
        }

        if (it + 1 < niter) {
            const int nb = (it + 1) & 1;
#pragma unroll
            for (int t = 0; t < 4; t++) {
                uint4 wa = { f2tf32(pa[t].x), f2tf32(pa[t].y), f2tf32(pa[t].z), f2tf32(pa[t].w) };
                *(uint4*)&As[nb][mL[t] * TSTRIDE + kqL[t]] = wa;
                uint4 wb = { f2tf32(pb[t].x), f2tf32(pb[t].y), f2tf32(pb[t].z), f2tf32(pb[t].w) };
                *(uint4*)&Bs[nb][mL[t] * TSTRIDE + kqL[t]] = wb;
            }
        }
        __syncthreads();
    }

#pragma unroll
    for (int mi = 0; mi < 4; mi++) {
#pragma unroll
        for (int ni = 0; ni < 4; ni++) {
            int r  = row0 + wm + 16 * mi + lr;
            int cc = col0 + wn + 8 * ni + 2 * lk;
            C[(size_t)r * N + cc]           = c[mi][ni][0];
            C[(size_t)r * N + cc + 1]       = c[mi][ni][1];
            C[(size_t)(r + 8) * N + cc]     = c[mi][ni][2];
            C[(size_t)(r + 8) * N + cc + 1] = c[mi][ni][3];
        }
    }
}

// ---------------------------------------------------------------------------
// RoPE (unchanged)
// ---------------------------------------------------------------------------
__global__ __launch_bounds__(256) void rope_kernel(
    float* __restrict__ q, float* __restrict__ k,
    const float* __restrict__ cosT, const float* __restrict__ sinT)
{
    const int bt  = blockIdx.x;
    const int t   = bt & (T_ - 1);
    const int tid = threadIdx.x;
    const float* cr = cosT + (size_t)t * HD_;
    const float* sr = sinT + (size_t)t * HD_;

    float* qrow = q + (size_t)bt * D_;
    for (int p = tid; p < H_ * 64; p += 256) {
        int h = p >> 6, i = p & 63;
        float* base = qrow + h * HD_;
        float q1 = base[i], q2 = base[i + 64];
        base[i]      = q1 * cr[i]      - q2 * sr[i];
        base[i + 64] = q2 * cr[i + 64] + q1 * sr[i + 64];
    }
    float* krow = k + (size_t)bt * KVD_;
    for (int p = tid; p < HKV_ * 64; p += 256) {
        int h = p >> 6, i = p & 63;
        float* base = krow + h * HD_;
        float k1 = base[i], k2 = base[i + 64];
        base[i]      = k1 * cr[i]      - k2 * sr[i];
        base[i + 64] = k2 * cr[i + 64] + k1 * sr[i + 64];
    }
}

// ---------------------------------------------------------------------------
// Tensor-core causal flash attention (tf32 mma.sync).
// Grid: (T/128, H, B). Block: 256 threads = 8 warps; warp w owns q-rows
// [w*16, w*16+16). BQ=128, BK=64, HD=128.
// Smem (u32 words): Ks[64][132] @0, Vs[64][136] @8448, Ps[128][68] @17152.
// Q staging [128][132] aliases Ks+Vs. Q fragments held in registers.
// ---------------------------------------------------------------------------
#define AT_VS_OFF 8448
#define AT_PS_OFF 17152
#define AT_WORDS  25856
#define ATTN_SMEM_BYTES (AT_WORDS * 4)   // 103424

__global__ __launch_bounds__(256, 1) void attn_tc_kernel(
    const float* __restrict__ q, const float* __restrict__ k,
    const float* __restrict__ v, float* __restrict__ o)
{
    extern __shared__ uint32_t sw[];
    uint32_t* Ks = sw;                 // [64][132]
    uint32_t* Vs = sw + AT_VS_OFF;     // [64][136]
    uint32_t* Ps = sw + AT_PS_OFF;     // [128][68]
    uint32_t* Qs = sw;                 // staging [128][132], aliases Ks+Vs

    const int qt  = blockIdx.x;
    const int h   = blockIdx.y;
    const int b   = blockIdx.z;
    const int kvh = h >> 2;
    const int q0  = qt * 128;
    const int tid  = threadIdx.x;
    const int lane = tid & 31;
    const int w    = tid >> 5;
    const int lr   = lane >> 2;
    const int lk   = lane & 3;
    const float scale = 0.08838834764831845f;   // 1/sqrt(128)

    // ---- stage Q (scaled, tf32) and pull fragments into registers ----
    {
        int row = tid >> 1;
        int d0  = (tid & 1) * 64;
        const float* src = q + (size_t)(b * T_ + q0 + row) * D_ + h * HD_ + d0;
#pragma unroll
        for (int j = 0; j < 64; j += 4) {
            float4 a = *(const float4*)(src + j);
            uint4 wv = { f2tf32(a.x * scale), f2tf32(a.y * scale),
                         f2tf32(a.z * scale), f2tf32(a.w * scale) };
            *(uint4*)&Qs[row * 132 + d0 + j] = wv;
        }
    }
    __syncthreads();

    uint32_t aQ[16][4];
#pragma unroll
    for (int kc = 0; kc < 16; kc++) {
        const uint32_t* base = &Qs[(w * 16 + lr) * 132 + kc * 8 + lk];
        aQ[kc][0] = base[0];
        aQ[kc][1] = base[8 * 132];
        aQ[kc][2] = base[4];
        aQ[kc][3] = base[8 * 132 + 4];
    }
    __syncthreads();

    float O[16][4];
#pragma unroll
    for (int nt = 0; nt < 16; nt++)
#pragma unroll
        for (int r = 0; r < 4; r++) O[nt][r] = 0.f;
    float m0 = -CUDART_INF_F, m1 = -CUDART_INF_F, l0 = 0.f, l1 = 0.f;

    const int row0g = q0 + w * 16 + lr;   // global q row (lower half)
    const int nkt = 2 * qt + 2;

    for (int kt = 0; kt < nkt; kt++) {
        const int k0 = kt * 64;
        // ---- load K,V tiles (convert to tf32) ----
        {
            int row = tid >> 2;
            int d0  = (tid & 3) * 32;
            const float* ksrc = k + (size_t)(b * T_ + k0 + row) * KVD_ + kvh * HD_ + d0;
            const float* vsrc = v + (size_t)(b * T_ + k0 + row) * KVD_ + kvh * HD_ + d0;
#pragma unroll
            for (int j = 0; j < 32; j += 4) {
                float4 a = *(const float4*)(ksrc + j);
                uint4 wa = { f2tf32(a.x), f2tf32(a.y), f2tf32(a.z), f2tf32(a.w) };
                *(uint4*)&Ks[row * 132 + d0 + j] = wa;
                float4 bb = *(const float4*)(vsrc + j);
                uint4 wb = { f2tf32(bb.x), f2tf32(bb.y), f2tf32(bb.z), f2tf32(bb.w) };
                *(uint4*)&Vs[row * 136 + d0 + j] = wb;
            }
        }
        __syncthreads();

        const bool active = (k0 <= q0 + w * 16 + 15);   // warp-uniform
        if (active) {
            // ---- S = Q K^T ----
            float s[8][4];
#pragma unroll
            for (int nt = 0; nt < 8; nt++)
#pragma unroll
                for (int r = 0; r < 4; r++) s[nt][r] = 0.f;

#pragma unroll
            for (int kc = 0; kc < 16; kc++) {
                uint32_t bf[8][2];
#pragma unroll
                for (int nt = 0; nt < 8; nt++) {
                    const uint32_t* kb = &Ks[(nt * 8 + lr) * 132 + kc * 8 + lk];
                    bf[nt][0] = kb[0];
                    bf[nt][1] = kb[4];
                }
#pragma unroll
                for (int nt = 0; nt < 8; nt++)
                    MMA_TF32(s[nt], aQ[kc], bf[nt]);
            }

            // ---- causal mask (only near diagonal) ----
            if (k0 + 63 > q0 + w * 16) {
#pragma unroll
                for (int nt = 0; nt < 8; nt++) {
                    int c0 = k0 + nt * 8 + 2 * lk;
                    if (c0     > row0g)     s[nt][0] = -CUDART_INF_F;
                    if (c0 + 1 > row0g)     s[nt][1] = -CUDART_INF_F;
                    if (c0     > row0g + 8) s[nt][2] = -CUDART_INF_F;
                    if (c0 + 1 > row0g + 8) s[nt][3] = -CUDART_INF_F;
                }
            }

            // ---- online softmax on fragment rows ----
            float mt0 = -CUDART_INF_F, mt1 = -CUDART_INF_F;
#pragma unroll
            for (int nt = 0; nt < 8; nt++) {
                mt0 = fmaxf(mt0, fmaxf(s[nt][0], s[nt][1]));
                mt1 = fmaxf(mt1, fmaxf(s[nt][2], s[nt][3]));
            }
#pragma unroll
            for (int off = 1; off <= 2; off <<= 1) {
                mt0 = fmaxf(mt0, __shfl_xor_sync(0xffffffffu, mt0, off));
                mt1 = fmaxf(mt1, __shfl_xor_sync(0xffffffffu, mt1, off));
            }
            float mn0 = fmaxf(m0, mt0), mn1 = fmaxf(m1, mt1);
            float al0 = __expf(m0 - mn0), al1 = __expf(m1 - mn1);
            m0 = mn0; m1 = mn1;

            float sum0 = 0.f, sum1 = 0.f;
#pragma unroll
            for (int nt = 0; nt < 8; nt++) {
                s[nt][0] = __expf(s[nt][0] - mn0); sum0 += s[nt][0];
                s[nt][1] = __expf(s[nt][1] - mn0); sum0 += s[nt][1];
                s[nt][2] = __expf(s[nt][2] - mn1); sum1 += s[nt][2];
                s[nt][3] = __expf(s[nt][3] - mn1); sum1 += s[nt][3];
            }
#pragma unroll
            for (int off = 1; off <= 2; off <<= 1) {
                sum0 += __shfl_xor_sync(0xffffffffu, sum0, off);
                sum1 += __shfl_xor_sync(0xffffffffu, sum1, off);
            }
            l0 = l0 * al0 + sum0;
            l1 = l1 * al1 + sum1;
#pragma unroll
            for (int nt = 0; nt < 16; nt++) {
                O[nt][0] *= al0; O[nt][1] *= al0;
                O[nt][2] *= al1; O[nt][3] *= al1;
            }

            // ---- P -> smem (tf32) ----
            __syncwarp();
#pragma unroll
            for (int nt = 0; nt < 8; nt++) {
                uint2 p0 = { f2tf32(s[nt][0]), f2tf32(s[nt][1]) };
                *(uint2*)&Ps[(w * 16 + lr) * 68 + nt * 8 + 2 * lk] = p0;
                uint2 p1 = { f2tf32(s[nt][2]), f2tf32(s[nt][3]) };
                *(uint2*)&Ps[(w * 16 + lr + 8) * 68 + nt * 8 + 2 * lk] = p1;
            }
            __syncwarp();

            // ---- O += P V ----
#pragma unroll
            for (int kc2 = 0; kc2 < 8; kc2++) {
                uint32_t pa[4];
                const uint32_t* pb = &Ps[(w * 16 + lr) * 68 + kc2 * 8 + lk];
                pa[0] = pb[0];
                pa[1] = pb[8 * 68];
                pa[2] = pb[4];
                pa[3] = pb[8 * 68 + 4];
#pragma unroll
                for (int nt = 0; nt < 16; nt++) {
                    uint32_t vb[2];
                    vb[0] = Vs[(kc2 * 8 + lk)     * 136 + nt * 8 + lr];
                    vb[1] = Vs[(kc2 * 8 + 4 + lk) * 136 + nt * 8 + lr];
                    MMA_TF32(O[nt], pa, vb);
                }
            }
        }
        __syncthreads();
    }

    // ---- epilogue ----
    float inv0 = 1.0f / l0, inv1 = 1.0f / l1;
    size_t r0base = (size_t)(b * T_ + q0 + w * 16 + lr) * D_ + h * HD_;
    size_t r1base = (size_t)(b * T_ + q0 + w * 16 + lr + 8) * D_ + h * HD_;
#pragma unroll
    for (int nt = 0; nt < 16; nt++) {
        float2 c0 = { O[nt][0] * inv0, O[nt][1] * inv0 };
        float2 c1 = { O[nt][2] * inv1, O[nt][3] * inv1 };
        *(float2*)&o[r0base + nt * 8 + 2 * lk] = c0;
        *(float2*)&o[r1base + nt * 8 + 2 * lk] = c1;
    }
}

// ---------------------------------------------------------------------------
// Launcher
// ---------------------------------------------------------------------------
extern "C" void kernel_launch(void* const* d_in, const int* in_sizes, int n_in,
                              void* d_out, int out_size)
{
    const float* x    = (const float*)d_in[0];
    const float* cosT = (const float*)d_in[1];
    const float* sinT = (const float*)d_in[2];
    const float* Wq   = (const float*)d_in[3];
    const float* Wk   = (const float*)d_in[4];
    const float* Wv   = (const float*)d_in[5];
    const float* Wo   = (const float*)d_in[6];
    float* out = (float*)d_out;

    float *gq, *gk, *gv, *gattn;
    cudaGetSymbolAddress((void**)&gq,    g_q);
    cudaGetSymbolAddress((void**)&gk,    g_k);
    cudaGetSymbolAddress((void**)&gv,    g_v);
    cudaGetSymbolAddress((void**)&gattn, g_attn);

    cudaFuncSetAttribute(attn_tc_kernel, cudaFuncAttributeMaxDynamicSharedMemorySize,
                         ATTN_SMEM_BYTES);
    cudaFuncSetAttribute(gemm_nt_tf32_kernel,
                         cudaFuncAttributeMaxDynamicSharedMemorySize,
                         GEMM_SMEM_BYTES);

    dim3 blk(256);
    dim3 gq_grid(D_ / 128, M_ / 128);
    dim3 gkv_grid(KVD_ / 128, M_ / 128);

    gemm_nt_tf32_kernel<<<gq_grid,  blk, GEMM_SMEM_BYTES>>>(x, Wq, gq, M_, D_,   D_);
    gemm_nt_tf32_kernel<<<gkv_grid, blk, GEMM_SMEM_BYTES>>>(x, Wk, gk, M_, KVD_, D_);
    gemm_nt_tf32_kernel<<<gkv_grid, blk, GEMM_SMEM_BYTES>>>(x, Wv, gv, M_, KVD_, D_);

    rope_kernel<<<M_, blk>>>(gq, gk, cosT, sinT);

    dim3 ga(T_ / 128, H_, B_);
    attn_tc_kernel<<<ga, blk, ATTN_SMEM_BYTES>>>(gq, gk, gv, gattn);

    gemm_nt_tf32_kernel<<<gq_grid, blk, GEMM_SMEM_BYTES>>>(gattn, Wo, out, M_, D_, D_);
}

// round 6
// speedup vs baseline: 3.1118x; 1.4139x over previous
#include <cuda_runtime.h>
#include <cuda_fp16.h>
#include <math_constants.h>
#include <stdint.h>

// Problem constants
#define B_   2
#define T_   2048
#define D_   2048
#define H_   16
#define HKV_ 4
#define HD_  128
#define G_   (H_ / HKV_)      // 4
#define M_   (B_ * T_)        // 4096
#define KVD_ (HKV_ * HD_)     // 512

// ---------------------------------------------------------------------------
// Scratch (device globals; no allocation allowed)
// ---------------------------------------------------------------------------
__device__ float g_q[(size_t)M_ * D_];     // 32 MB
__device__ float g_k[(size_t)M_ * KVD_];   //  8 MB
__device__ float g_v[(size_t)M_ * KVD_];   //  8 MB
__device__ float g_attn[(size_t)M_ * D_];  // 32 MB

// ---------------------------------------------------------------------------
// Helpers
// ---------------------------------------------------------------------------
__device__ __forceinline__ uint32_t f2tf32(float x) {
    uint32_t r;
    asm("cvt.rna.tf32.f32 %0, %1;" : "=r"(r) : "f"(x));
    return r;
}

__device__ __forceinline__ uint32_t pk_h2(float lo, float hi) {
    half2 h = __floats2half2_rn(lo, hi);
    return *(uint32_t*)&h;
}

#define MMA_TF32(c, a, b)                                                     \
    asm volatile(                                                             \
        "mma.sync.aligned.m16n8k8.row.col.f32.tf32.tf32.f32 "                 \
        "{%0,%1,%2,%3},{%4,%5,%6,%7},{%8,%9},{%0,%1,%2,%3};"                  \
        : "+f"((c)[0]), "+f"((c)[1]), "+f"((c)[2]), "+f"((c)[3])              \
        : "r"((a)[0]), "r"((a)[1]), "r"((a)[2]), "r"((a)[3]),                 \
          "r"((b)[0]), "r"((b)[1]))

#define MMA_F16(c, a, b)                                                      \
    asm volatile(                                                             \
        "mma.sync.aligned.m16n8k16.row.col.f32.f16.f16.f32 "                  \
        "{%0,%1,%2,%3},{%4,%5,%6,%7},{%8,%9},{%0,%1,%2,%3};"                  \
        : "+f"((c)[0]), "+f"((c)[1]), "+f"((c)[2]), "+f"((c)[3])              \
        : "r"((a)[0]), "r"((a)[1]), "r"((a)[2]), "r"((a)[3]),                 \
          "r"((b)[0]), "r"((b)[1]))

// ---------------------------------------------------------------------------
// fp16 tensor-core GEMM: C[M,N] = A[M,K] @ Bm[N,K]^T
// BM=BN=128, BK=32 (floats), 256 threads (8 warps 2x4), warp tile 64x32.
// Smem: half2 words, row stride 18 words (16 data + 2 pad) — conflict-free
// a/b fragment LDS (banks (r*18+lk)%32 all distinct). Double-buffered with
// register prefetch; __floats2half2_rn on the STS path (round-to-nearest).
// ---------------------------------------------------------------------------
#define HSTRIDE 18
#define HTILE_WORDS (128 * HSTRIDE)              // 2304 u32 per tile
#define GEMM_SMEM_BYTES (4 * HTILE_WORDS * 4)    // 36864 B

__global__ __launch_bounds__(256) void gemm_nt_f16_kernel(
    const float* __restrict__ A, const float* __restrict__ Bm,
    float* __restrict__ C, int M, int N, int K)
{
    extern __shared__ uint32_t smw[];
    uint32_t* As[2] = { smw,                   smw + HTILE_WORDS };
    uint32_t* Bs[2] = { smw + 2 * HTILE_WORDS, smw + 3 * HTILE_WORDS };

    const int tid  = threadIdx.x;
    const int lane = tid & 31;
    const int warp = tid >> 5;
    const int row0 = blockIdx.y * 128;
    const int col0 = blockIdx.x * 128;
    const int wm   = (warp >> 2) * 64;   // 0 / 64
    const int wn   = (warp & 3) * 32;    // 0..96
    const int lk   = lane & 3;
    const int lr   = lane >> 2;

    // per-thread global-load coords: idx -> m = idx>>3, float col = (idx&7)*4
    int mL[4], kqL[4], kwL[4];
#pragma unroll
    for (int t = 0; t < 4; t++) {
        int idx = tid + 256 * t;
        mL[t]  = idx >> 3;
        kqL[t] = (idx & 7) << 2;    // float index 0..28
        kwL[t] = (idx & 7) << 1;    // half2 word index 0..14
    }

    float c[4][4][4];
#pragma unroll
    for (int mi = 0; mi < 4; mi++)
#pragma unroll
        for (int ni = 0; ni < 4; ni++)
#pragma unroll
            for (int r = 0; r < 4; r++) c[mi][ni][r] = 0.f;

    const int niter = K >> 5;
    float4 pa[4], pb[4];

    // prologue: tile 0 -> regs -> smem buf 0
#pragma unroll
    for (int t = 0; t < 4; t++) {
        pa[t] = *(const float4*)&A [(size_t)(row0 + mL[t]) * K + kqL[t]];
        pb[t] = *(const float4*)&Bm[(size_t)(col0 + mL[t]) * K + kqL[t]];
    }
#pragma unroll
    for (int t = 0; t < 4; t++) {
        uint2 wa = { pk_h2(pa[t].x, pa[t].y), pk_h2(pa[t].z, pa[t].w) };
        *(uint2*)&As[0][mL[t] * HSTRIDE + kwL[t]] = wa;
        uint2 wb = { pk_h2(pb[t].x, pb[t].y), pk_h2(pb[t].z, pb[t].w) };
        *(uint2*)&Bs[0][mL[t] * HSTRIDE + kwL[t]] = wb;
    }
    __syncthreads();

    for (int it = 0; it < niter; ++it) {
        const int cur = it & 1;
        if (it + 1 < niter) {
            const int k0 = (it + 1) << 5;
#pragma unroll
            for (int t = 0; t < 4; t++) {
                pa[t] = *(const float4*)&A [(size_t)(row0 + mL[t]) * K + k0 + kqL[t]];
                pb[t] = *(const float4*)&Bm[(size_t)(col0 + mL[t]) * K + k0 + kqL[t]];
            }
        }

        const uint32_t* __restrict__ as = As[cur];
        const uint32_t* __restrict__ bs = Bs[cur];
#pragma unroll
        for (int s = 0; s < 2; s++) {            // two k16 steps per iter
            const int kw = s * 8;
            uint32_t af[4][4], bf[4][2];
#pragma unroll
            for (int mi = 0; mi < 4; mi++) {
                int m = wm + 16 * mi;
                af[mi][0] = as[(m + lr)     * HSTRIDE + kw + lk];
                af[mi][1] = as[(m + lr + 8) * HSTRIDE + kw + lk];
                af[mi][2] = as[(m + lr)     * HSTRIDE + kw + lk + 4];
                af[mi][3] = as[(m + lr + 8) * HSTRIDE + kw + lk + 4];
            }
#pragma unroll
            for (int ni = 0; ni < 4; ni++) {
                int n = wn + 8 * ni;
                bf[ni][0] = bs[(n + lr) * HSTRIDE + kw + lk];
                bf[ni][1] = bs[(n + lr) * HSTRIDE + kw + lk + 4];
            }
#pragma unroll
            for (int mi = 0; mi < 4; mi++)
#pragma unroll
                for (int ni = 0; ni < 4; ni++)
                    MMA_F16(c[mi][ni], af[mi], bf[ni]);
        }

        if (it + 1 < niter) {
            const int nb = (it + 1) & 1;
#pragma unroll
            for (int t = 0; t < 4; t++) {
                uint2 wa = { pk_h2(pa[t].x, pa[t].y), pk_h2(pa[t].z, pa[t].w) };
                *(uint2*)&As[nb][mL[t] * HSTRIDE + kwL[t]] = wa;
                uint2 wb = { pk_h2(pb[t].x, pb[t].y), pk_h2(pb[t].z, pb[t].w) };
                *(uint2*)&Bs[nb][mL[t] * HSTRIDE + kwL[t]] = wb;
            }
        }
        __syncthreads();
    }

    // epilogue
#pragma unroll
    for (int mi = 0; mi < 4; mi++) {
#pragma unroll
        for (int ni = 0; ni < 4; ni++) {
            int r  = row0 + wm + 16 * mi + lr;
            int cc = col0 + wn + 8 * ni + 2 * lk;
            C[(size_t)r * N + cc]           = c[mi][ni][0];
            C[(size_t)r * N + cc + 1]       = c[mi][ni][1];
            C[(size_t)(r + 8) * N + cc]     = c[mi][ni][2];
            C[(size_t)(r + 8) * N + cc + 1] = c[mi][ni][3];
        }
    }
}

// ---------------------------------------------------------------------------
// RoPE (unchanged)
// ---------------------------------------------------------------------------
__global__ __launch_bounds__(256) void rope_kernel(
    float* __restrict__ q, float* __restrict__ k,
    const float* __restrict__ cosT, const float* __restrict__ sinT)
{
    const int bt  = blockIdx.x;
    const int t   = bt & (T_ - 1);
    const int tid = threadIdx.x;
    const float* cr = cosT + (size_t)t * HD_;
    const float* sr = sinT + (size_t)t * HD_;

    float* qrow = q + (size_t)bt * D_;
    for (int p = tid; p < H_ * 64; p += 256) {
        int h = p >> 6, i = p & 63;
        float* base = qrow + h * HD_;
        float q1 = base[i], q2 = base[i + 64];
        base[i]      = q1 * cr[i]      - q2 * sr[i];
        base[i + 64] = q2 * cr[i + 64] + q1 * sr[i + 64];
    }
    float* krow = k + (size_t)bt * KVD_;
    for (int p = tid; p < HKV_ * 64; p += 256) {
        int h = p >> 6, i = p & 63;
        float* base = krow + h * HD_;
        float k1 = base[i], k2 = base[i + 64];
        base[i]      = k1 * cr[i]      - k2 * sr[i];
        base[i + 64] = k2 * cr[i + 64] + k1 * sr[i + 64];
    }
}

// ---------------------------------------------------------------------------
// Tensor-core causal flash attention (tf32 mma.sync) — unchanged from R3.
// ---------------------------------------------------------------------------
#define AT_VS_OFF 8448
#define AT_PS_OFF 17152
#define AT_WORDS  25856
#define ATTN_SMEM_BYTES (AT_WORDS * 4)   // 103424

__global__ __launch_bounds__(256, 1) void attn_tc_kernel(
    const float* __restrict__ q, const float* __restrict__ k,
    const float* __restrict__ v, float* __restrict__ o)
{
    extern __shared__ uint32_t sw[];
    uint32_t* Ks = sw;                 // [64][132]
    uint32_t* Vs = sw + AT_VS_OFF;     // [64][136]
    uint32_t* Ps = sw + AT_PS_OFF;     // [128][68]
    uint32_t* Qs = sw;                 // staging [128][132], aliases Ks+Vs

    const int qt  = blockIdx.x;
    const int h   = blockIdx.y;
    const int b   = blockIdx.z;
    const int kvh = h >> 2;
    const int q0  = qt * 128;
    const int tid  = threadIdx.x;
    const int lane = tid & 31;
    const int w    = tid >> 5;
    const int lr   = lane >> 2;
    const int lk   = lane & 3;
    const float scale = 0.08838834764831845f;   // 1/sqrt(128)

    {
        int row = tid >> 1;
        int d0  = (tid & 1) * 64;
        const float* src = q + (size_t)(b * T_ + q0 + row) * D_ + h * HD_ + d0;
#pragma unroll
        for (int j = 0; j < 64; j += 4) {
            float4 a = *(const float4*)(src + j);
            uint4 wv = { f2tf32(a.x * scale), f2tf32(a.y * scale),
                         f2tf32(a.z * scale), f2tf32(a.w * scale) };
            *(uint4*)&Qs[row * 132 + d0 + j] = wv;
        }
    }
    __syncthreads();

    uint32_t aQ[16][4];
#pragma unroll
    for (int kc = 0; kc < 16; kc++) {
        const uint32_t* base = &Qs[(w * 16 + lr) * 132 + kc * 8 + lk];
        aQ[kc][0] = base[0];
        aQ[kc][1] = base[8 * 132];
        aQ[kc][2] = base[4];
        aQ[kc][3] = base[8 * 132 + 4];
    }
    __syncthreads();

    float O[16][4];
#pragma unroll
    for (int nt = 0; nt < 16; nt++)
#pragma unroll
        for (int r = 0; r < 4; r++) O[nt][r] = 0.f;
    float m0 = -CUDART_INF_F, m1 = -CUDART_INF_F, l0 = 0.f, l1 = 0.f;

    const int row0g = q0 + w * 16 + lr;
    const int nkt = 2 * qt + 2;

    for (int kt = 0; kt < nkt; kt++) {
        const int k0 = kt * 64;
        {
            int row = tid >> 2;
            int d0  = (tid & 3) * 32;
            const float* ksrc = k + (size_t)(b * T_ + k0 + row) * KVD_ + kvh * HD_ + d0;
            const float* vsrc = v + (size_t)(b * T_ + k0 + row) * KVD_ + kvh * HD_ + d0;
#pragma unroll
            for (int j = 0; j < 32; j += 4) {
                float4 a = *(const float4*)(ksrc + j);
                uint4 wa = { f2tf32(a.x), f2tf32(a.y), f2tf32(a.z), f2tf32(a.w) };
                *(uint4*)&Ks[row * 132 + d0 + j] = wa;
                float4 bb = *(const float4*)(vsrc + j);
                uint4 wb = { f2tf32(bb.x), f2tf32(bb.y), f2tf32(bb.z), f2tf32(bb.w) };
                *(uint4*)&Vs[row * 136 + d0 + j] = wb;
            }
        }
        __syncthreads();

        const bool active = (k0 <= q0 + w * 16 + 15);
        if (active) {
            float s[8][4];
#pragma unroll
            for (int nt = 0; nt < 8; nt++)
#pragma unroll
                for (int r = 0; r < 4; r++) s[nt][r] = 0.f;

#pragma unroll
            for (int kc = 0; kc < 16; kc++) {
                uint32_t bf[8][2];
#pragma unroll
                for (int nt = 0; nt < 8; nt++) {
                    const uint32_t* kb = &Ks[(nt * 8 + lr) * 132 + kc * 8 + lk];
                    bf[nt][0] = kb[0];
                    bf[nt][1] = kb[4];
                }
#pragma unroll
                for (int nt = 0; nt < 8; nt++)
                    MMA_TF32(s[nt], aQ[kc], bf[nt]);
            }

            if (k0 + 63 > q0 + w * 16) {
#pragma unroll
                for (int nt = 0; nt < 8; nt++) {
                    int c0 = k0 + nt * 8 + 2 * lk;
                    if (c0     > row0g)     s[nt][0] = -CUDART_INF_F;
                    if (c0 + 1 > row0g)     s[nt][1] = -CUDART_INF_F;
                    if (c0     > row0g + 8) s[nt][2] = -CUDART_INF_F;
                    if (c0 + 1 > row0g + 8) s[nt][3] = -CUDART_INF_F;
                }
            }

            float mt0 = -CUDART_INF_F, mt1 = -CUDART_INF_F;
#pragma unroll
            for (int nt = 0; nt < 8; nt++) {
                mt0 = fmaxf(mt0, fmaxf(s[nt][0], s[nt][1]));
                mt1 = fmaxf(mt1, fmaxf(s[nt][2], s[nt][3]));
            }
#pragma unroll
            for (int off = 1; off <= 2; off <<= 1) {
                mt0 = fmaxf(mt0, __shfl_xor_sync(0xffffffffu, mt0, off));
                mt1 = fmaxf(mt1, __shfl_xor_sync(0xffffffffu, mt1, off));
            }
            float mn0 = fmaxf(m0, mt0), mn1 = fmaxf(m1, mt1);
            float al0 = __expf(m0 - mn0), al1 = __expf(m1 - mn1);
            m0 = mn0; m1 = mn1;

            float sum0 = 0.f, sum1 = 0.f;
#pragma unroll
            for (int nt = 0; nt < 8; nt++) {
                s[nt][0] = __expf(s[nt][0] - mn0); sum0 += s[nt][0];
                s[nt][1] = __expf(s[nt][1] - mn0); sum0 += s[nt][1];
                s[nt][2] = __expf(s[nt][2] - mn1); sum1 += s[nt][2];
                s[nt][3] = __expf(s[nt][3] - mn1); sum1 += s[nt][3];
            }
#pragma unroll
            for (int off = 1; off <= 2; off <<= 1) {
                sum0 += __shfl_xor_sync(0xffffffffu, sum0, off);
                sum1 += __shfl_xor_sync(0xffffffffu, sum1, off);
            }
            l0 = l0 * al0 + sum0;
            l1 = l1 * al1 + sum1;
#pragma unroll
            for (int nt = 0; nt < 16; nt++) {
                O[nt][0] *= al0; O[nt][1] *= al0;
                O[nt][2] *= al1; O[nt][3] *= al1;
            }

            __syncwarp();
#pragma unroll
            for (int nt = 0; nt < 8; nt++) {
                uint2 p0 = { f2tf32(s[nt][0]), f2tf32(s[nt][1]) };
                *(uint2*)&Ps[(w * 16 + lr) * 68 + nt * 8 + 2 * lk] = p0;
                uint2 p1 = { f2tf32(s[nt][2]), f2tf32(s[nt][3]) };
                *(uint2*)&Ps[(w * 16 + lr + 8) * 68 + nt * 8 + 2 * lk] = p1;
            }
            __syncwarp();

#pragma unroll
            for (int kc2 = 0; kc2 < 8; kc2++) {
                uint32_t pa[4];
                const uint32_t* pb = &Ps[(w * 16 + lr) * 68 + kc2 * 8 + lk];
                pa[0] = pb[0];
                pa[1] = pb[8 * 68];
                pa[2] = pb[4];
                pa[3] = pb[8 * 68 + 4];
#pragma unroll
                for (int nt = 0; nt < 16; nt++) {
                    uint32_t vb[2];
                    vb[0] = Vs[(kc2 * 8 + lk)     * 136 + nt * 8 + lr];
                    vb[1] = Vs[(kc2 * 8 + 4 + lk) * 136 + nt * 8 + lr];
                    MMA_TF32(O[nt], pa, vb);
                }
            }
        }
        __syncthreads();
    }

    float inv0 = 1.0f / l0, inv1 = 1.0f / l1;
    size_t r0base = (size_t)(b * T_ + q0 + w * 16 + lr) * D_ + h * HD_;
    size_t r1base = (size_t)(b * T_ + q0 + w * 16 + lr + 8) * D_ + h * HD_;
#pragma unroll
    for (int nt = 0; nt < 16; nt++) {
        float2 c0 = { O[nt][0] * inv0, O[nt][1] * inv0 };
        float2 c1 = { O[nt][2] * inv1, O[nt][3] * inv1 };
        *(float2*)&o[r0base + nt * 8 + 2 * lk] = c0;
        *(float2*)&o[r1base + nt * 8 + 2 * lk] = c1;
    }
}

// ---------------------------------------------------------------------------
// Launcher
// ---------------------------------------------------------------------------
extern "C" void kernel_launch(void* const* d_in, const int* in_sizes, int n_in,
                              void* d_out, int out_size)
{
    const float* x    = (const float*)d_in[0];
    const float* cosT = (const float*)d_in[1];
    const float* sinT = (const float*)d_in[2];
    const float* Wq   = (const float*)d_in[3];
    const float* Wk   = (const float*)d_in[4];
    const float* Wv   = (const float*)d_in[5];
    const float* Wo   = (const float*)d_in[6];
    float* out = (float*)d_out;

    float *gq, *gk, *gv, *gattn;
    cudaGetSymbolAddress((void**)&gq,    g_q);
    cudaGetSymbolAddress((void**)&gk,    g_k);
    cudaGetSymbolAddress((void**)&gv,    g_v);
    cudaGetSymbolAddress((void**)&gattn, g_attn);

    cudaFuncSetAttribute(attn_tc_kernel, cudaFuncAttributeMaxDynamicSharedMemorySize,
                         ATTN_SMEM_BYTES);
    cudaFuncSetAttribute(gemm_nt_f16_kernel,
                         cudaFuncAttributeMaxDynamicSharedMemorySize,
                         GEMM_SMEM_BYTES);

    dim3 blk(256);
    dim3 gq_grid(D_ / 128, M_ / 128);
    dim3 gkv_grid(KVD_ / 128, M_ / 128);

    gemm_nt_f16_kernel<<<gq_grid,  blk, GEMM_SMEM_BYTES>>>(x, Wq, gq, M_, D_,   D_);
    gemm_nt_f16_kernel<<<gkv_grid, blk, GEMM_SMEM_BYTES>>>(x, Wk, gk, M_, KVD_, D_);
    gemm_nt_f16_kernel<<<gkv_grid, blk, GEMM_SMEM_BYTES>>>(x, Wv, gv, M_, KVD_, D_);

    rope_kernel<<<M_, blk>>>(gq, gk, cosT, sinT);

    dim3 ga(T_ / 128, H_, B_);
    attn_tc_kernel<<<ga, blk, ATTN_SMEM_BYTES>>>(gq, gk, gv, gattn);

    gemm_nt_f16_kernel<<<gq_grid, blk, GEMM_SMEM_BYTES>>>(gattn, Wo, out, M_, D_, D_);
}

// round 7
// speedup vs baseline: 3.5348x; 1.1359x over previous
#include <cuda_runtime.h>
#include <cuda_fp16.h>
#include <math_constants.h>
#include <stdint.h>

// Problem constants
#define B_   2
#define T_   2048
#define D_   2048
#define H_   16
#define HKV_ 4
#define HD_  128
#define G_   (H_ / HKV_)      // 4
#define M_   (B_ * T_)        // 4096
#define KVD_ (HKV_ * HD_)     // 512

// ---------------------------------------------------------------------------
// Scratch (device globals; no allocation allowed)
// ---------------------------------------------------------------------------
__device__ float g_q[(size_t)M_ * D_];     // 32 MB
__device__ float g_k[(size_t)M_ * KVD_];   //  8 MB
__device__ float g_v[(size_t)M_ * KVD_];   //  8 MB
__device__ float g_attn[(size_t)M_ * D_];  // 32 MB

// ---------------------------------------------------------------------------
// Helpers
// ---------------------------------------------------------------------------
__device__ __forceinline__ uint32_t pk_h2(float lo, float hi) {
    half2 h = __floats2half2_rn(lo, hi);
    return *(uint32_t*)&h;
}

#define MMA_F16(c, a, b)                                                      \
    asm volatile(                                                             \
        "mma.sync.aligned.m16n8k16.row.col.f32.f16.f16.f32 "                  \
        "{%0,%1,%2,%3},{%4,%5,%6,%7},{%8,%9},{%0,%1,%2,%3};"                  \
        : "+f"((c)[0]), "+f"((c)[1]), "+f"((c)[2]), "+f"((c)[3])              \
        : "r"((a)[0]), "r"((a)[1]), "r"((a)[2]), "r"((a)[3]),                 \
          "r"((b)[0]), "r"((b)[1]))

// ---------------------------------------------------------------------------
// fp16 tensor-core GEMM: C[M,N] = A[M,K] @ Bm[N,K]^T  (unchanged from R6)
// ---------------------------------------------------------------------------
#define HSTRIDE 18
#define HTILE_WORDS (128 * HSTRIDE)              // 2304 u32 per tile
#define GEMM_SMEM_BYTES (4 * HTILE_WORDS * 4)    // 36864 B

__global__ __launch_bounds__(256) void gemm_nt_f16_kernel(
    const float* __restrict__ A, const float* __restrict__ Bm,
    float* __restrict__ C, int M, int N, int K)
{
    extern __shared__ uint32_t smw[];
    uint32_t* As[2] = { smw,                   smw + HTILE_WORDS };
    uint32_t* Bs[2] = { smw + 2 * HTILE_WORDS, smw + 3 * HTILE_WORDS };

    const int tid  = threadIdx.x;
    const int lane = tid & 31;
    const int warp = tid >> 5;
    const int row0 = blockIdx.y * 128;
    const int col0 = blockIdx.x * 128;
    const int wm   = (warp >> 2) * 64;
    const int wn   = (warp & 3) * 32;
    const int lk   = lane & 3;
    const int lr   = lane >> 2;

    int mL[4], kqL[4], kwL[4];
#pragma unroll
    for (int t = 0; t < 4; t++) {
        int idx = tid + 256 * t;
        mL[t]  = idx >> 3;
        kqL[t] = (idx & 7) << 2;
        kwL[t] = (idx & 7) << 1;
    }

    float c[4][4][4];
#pragma unroll
    for (int mi = 0; mi < 4; mi++)
#pragma unroll
        for (int ni = 0; ni < 4; ni++)
#pragma unroll
            for (int r = 0; r < 4; r++) c[mi][ni][r] = 0.f;

    const int niter = K >> 5;
    float4 pa[4], pb[4];

#pragma unroll
    for (int t = 0; t < 4; t++) {
        pa[t] = *(const float4*)&A [(size_t)(row0 + mL[t]) * K + kqL[t]];
        pb[t] = *(const float4*)&Bm[(size_t)(col0 + mL[t]) * K + kqL[t]];
    }
#pragma unroll
    for (int t = 0; t < 4; t++) {
        uint2 wa = { pk_h2(pa[t].x, pa[t].y), pk_h2(pa[t].z, pa[t].w) };
        *(uint2*)&As[0][mL[t] * HSTRIDE + kwL[t]] = wa;
        uint2 wb = { pk_h2(pb[t].x, pb[t].y), pk_h2(pb[t].z, pb[t].w) };
        *(uint2*)&Bs[0][mL[t] * HSTRIDE + kwL[t]] = wb;
    }
    __syncthreads();

    for (int it = 0; it < niter; ++it) {
        const int cur = it & 1;
        if (it + 1 < niter) {
            const int k0 = (it + 1) << 5;
#pragma unroll
            for (int t = 0; t < 4; t++) {
                pa[t] = *(const float4*)&A [(size_t)(row0 + mL[t]) * K + k0 + kqL[t]];
                pb[t] = *(const float4*)&Bm[(size_t)(col0 + mL[t]) * K + k0 + kqL[t]];
            }
        }

        const uint32_t* __restrict__ as = As[cur];
        const uint32_t* __restrict__ bs = Bs[cur];
#pragma unroll
        for (int s = 0; s < 2; s++) {
            const int kw = s * 8;
            uint32_t af[4][4], bf[4][2];
#pragma unroll
            for (int mi = 0; mi < 4; mi++) {
                int m = wm + 16 * mi;
                af[mi][0] = as[(m + lr)     * HSTRIDE + kw + lk];
                af[mi][1] = as[(m + lr + 8) * HSTRIDE + kw + lk];
                af[mi][2] = as[(m + lr)     * HSTRIDE + kw + lk + 4];
                af[mi][3] = as[(m + lr + 8) * HSTRIDE + kw + lk + 4];
            }
#pragma unroll
            for (int ni = 0; ni < 4; ni++) {
                int n = wn + 8 * ni;
                bf[ni][0] = bs[(n + lr) * HSTRIDE + kw + lk];
                bf[ni][1] = bs[(n + lr) * HSTRIDE + kw + lk + 4];
            }
#pragma unroll
            for (int mi = 0; mi < 4; mi++)
#pragma unroll
                for (int ni = 0; ni < 4; ni++)
                    MMA_F16(c[mi][ni], af[mi], bf[ni]);
        }

        if (it + 1 < niter) {
            const int nb = (it + 1) & 1;
#pragma unroll
            for (int t = 0; t < 4; t++) {
                uint2 wa = { pk_h2(pa[t].x, pa[t].y), pk_h2(pa[t].z, pa[t].w) };
                *(uint2*)&As[nb][mL[t] * HSTRIDE + kwL[t]] = wa;
                uint2 wb = { pk_h2(pb[t].x, pb[t].y), pk_h2(pb[t].z, pb[t].w) };
                *(uint2*)&Bs[nb][mL[t] * HSTRIDE + kwL[t]] = wb;
            }
        }
        __syncthreads();
    }

#pragma unroll
    for (int mi = 0; mi < 4; mi++) {
#pragma unroll
        for (int ni = 0; ni < 4; ni++) {
            int r  = row0 + wm + 16 * mi + lr;
            int cc = col0 + wn + 8 * ni + 2 * lk;
            C[(size_t)r * N + cc]           = c[mi][ni][0];
            C[(size_t)r * N + cc + 1]       = c[mi][ni][1];
            C[(size_t)(r + 8) * N + cc]     = c[mi][ni][2];
            C[(size_t)(r + 8) * N + cc + 1] = c[mi][ni][3];
        }
    }
}

// ---------------------------------------------------------------------------
// RoPE (unchanged)
// ---------------------------------------------------------------------------
__global__ __launch_bounds__(256) void rope_kernel(
    float* __restrict__ q, float* __restrict__ k,
    const float* __restrict__ cosT, const float* __restrict__ sinT)
{
    const int bt  = blockIdx.x;
    const int t   = bt & (T_ - 1);
    const int tid = threadIdx.x;
    const float* cr = cosT + (size_t)t * HD_;
    const float* sr = sinT + (size_t)t * HD_;

    float* qrow = q + (size_t)bt * D_;
    for (int p = tid; p < H_ * 64; p += 256) {
        int h = p >> 6, i = p & 63;
        float* base = qrow + h * HD_;
        float q1 = base[i], q2 = base[i + 64];
        base[i]      = q1 * cr[i]      - q2 * sr[i];
        base[i + 64] = q2 * cr[i + 64] + q1 * sr[i + 64];
    }
    float* krow = k + (size_t)bt * KVD_;
    for (int p = tid; p < HKV_ * 64; p += 256) {
        int h = p >> 6, i = p & 63;
        float* base = krow + h * HD_;
        float k1 = base[i], k2 = base[i + 64];
        base[i]      = k1 * cr[i]      - k2 * sr[i];
        base[i + 64] = k2 * cr[i + 64] + k1 * sr[i + 64];
    }
}

// ---------------------------------------------------------------------------
// fp16 tensor-core causal flash attention (m16n8k16).
// Grid: (T/128, H, B). Block: 256 threads = 8 warps; warp w owns q-rows
// [w*16, w*16+16). BQ=128, BK=64, HD=128.
// Smem (u32 words): Ks[64][68] half2 d-packed @0, Vs[128][36] half2
// key-packed (transposed) @4352. Q staging [128][68] aliases both.
// P stays in registers (S C-frag == PV A-frag layout after half2 pack).
// ---------------------------------------------------------------------------
#define AT_VS_OFF 4352
#define AT_WORDS  8960
#define ATTN_SMEM_BYTES (AT_WORDS * 4)   // 35840

__global__ __launch_bounds__(256) void attn_f16_kernel(
    const float* __restrict__ q, const float* __restrict__ k,
    const float* __restrict__ v, float* __restrict__ o)
{
    extern __shared__ uint32_t sw[];
    uint32_t* Ks = sw;                 // [64][68]
    uint32_t* Vs = sw + AT_VS_OFF;     // [128][36]
    uint32_t* Qs = sw;                 // staging [128][68], aliases Ks+Vs

    const int qt  = blockIdx.x;
    const int h   = blockIdx.y;
    const int b   = blockIdx.z;
    const int kvh = h >> 2;
    const int q0  = qt * 128;
    const int tid  = threadIdx.x;
    const int lane = tid & 31;
    const int w    = tid >> 5;
    const int lr   = lane >> 2;
    const int lk   = lane & 3;
    const float scale = 0.08838834764831845f;   // 1/sqrt(128)

    // ---- stage Q (scaled, fp16) and pull A-fragments into registers ----
    {
        int row = tid >> 1;
        int d0  = (tid & 1) * 64;
        const float* src = q + (size_t)(b * T_ + q0 + row) * D_ + h * HD_ + d0;
#pragma unroll
        for (int j = 0; j < 64; j += 4) {
            float4 a = *(const float4*)(src + j);
            uint2 wv = { pk_h2(a.x * scale, a.y * scale),
                         pk_h2(a.z * scale, a.w * scale) };
            *(uint2*)&Qs[row * 68 + ((d0 + j) >> 1)] = wv;
        }
    }
    __syncthreads();

    uint32_t aQ[8][4];
#pragma unroll
    for (int c = 0; c < 8; c++) {
        const uint32_t* base = &Qs[(w * 16 + lr) * 68 + c * 8 + lk];
        aQ[c][0] = base[0];
        aQ[c][1] = base[8 * 68];
        aQ[c][2] = base[4];
        aQ[c][3] = base[8 * 68 + 4];
    }
    __syncthreads();

    float O[16][4];
#pragma unroll
    for (int nt = 0; nt < 16; nt++)
#pragma unroll
        for (int r = 0; r < 4; r++) O[nt][r] = 0.f;
    float m0 = -CUDART_INF_F, m1 = -CUDART_INF_F, l0 = 0.f, l1 = 0.f;

    const int row0g = q0 + w * 16 + lr;
    const int nkt = 2 * qt + 2;

    for (int kt = 0; kt < nkt; kt++) {
        const int k0 = kt * 64;
        // ---- load K (half2, d-packed) and V transposed (half2, key-packed) ----
        {
            int row = tid >> 2;                 // key 0..63
            int d0  = (tid & 3) * 32;
            const float* ksrc = k + (size_t)(b * T_ + k0 + row) * KVD_ + kvh * HD_ + d0;
            const float* vsrc = v + (size_t)(b * T_ + k0 + row) * KVD_ + kvh * HD_ + d0;
            __half* Vh = (__half*)Vs;           // rows = d, stride 72 halves
#pragma unroll
            for (int j = 0; j < 32; j += 4) {
                float4 a = *(const float4*)(ksrc + j);
                uint2 wa = { pk_h2(a.x, a.y), pk_h2(a.z, a.w) };
                *(uint2*)&Ks[row * 68 + ((d0 + j) >> 1)] = wa;
                float4 bb = *(const float4*)(vsrc + j);
                Vh[(d0 + j + 0) * 72 + row] = __float2half_rn(bb.x);
                Vh[(d0 + j + 1) * 72 + row] = __float2half_rn(bb.y);
                Vh[(d0 + j + 2) * 72 + row] = __float2half_rn(bb.z);
                Vh[(d0 + j + 3) * 72 + row] = __float2half_rn(bb.w);
            }
        }
        __syncthreads();

        const bool active = (k0 <= q0 + w * 16 + 15);   // warp-uniform
        if (active) {
            // ---- S = Q K^T ----
            float s[8][4];
#pragma unroll
            for (int nt = 0; nt < 8; nt++)
#pragma unroll
                for (int r = 0; r < 4; r++) s[nt][r] = 0.f;

#pragma unroll
            for (int c = 0; c < 8; c++) {
                uint32_t bf[8][2];
#pragma unroll
                for (int nt = 0; nt < 8; nt++) {
                    const uint32_t* kb = &Ks[(nt * 8 + lr) * 68 + c * 8 + lk];
                    bf[nt][0] = kb[0];
                    bf[nt][1] = kb[4];
                }
#pragma unroll
                for (int nt = 0; nt < 8; nt++)
                    MMA_F16(s[nt], aQ[c], bf[nt]);
            }

            // ---- causal mask (only near diagonal) ----
            if (k0 + 63 > q0 + w * 16) {
#pragma unroll
                for (int nt = 0; nt < 8; nt++) {
                    int c0 = k0 + nt * 8 + 2 * lk;
                    if (c0     > row0g)     s[nt][0] = -CUDART_INF_F;
                    if (c0 + 1 > row0g)     s[nt][1] = -CUDART_INF_F;
                    if (c0     > row0g + 8) s[nt][2] = -CUDART_INF_F;
                    if (c0 + 1 > row0g + 8) s[nt][3] = -CUDART_INF_F;
                }
            }

            // ---- online softmax on fragment rows ----
            float mt0 = -CUDART_INF_F, mt1 = -CUDART_INF_F;
#pragma unroll
            for (int nt = 0; nt < 8; nt++) {
                mt0 = fmaxf(mt0, fmaxf(s[nt][0], s[nt][1]));
                mt1 = fmaxf(mt1, fmaxf(s[nt][2], s[nt][3]));
            }
#pragma unroll
            for (int off = 1; off <= 2; off <<= 1) {
                mt0 = fmaxf(mt0, __shfl_xor_sync(0xffffffffu, mt0, off));
                mt1 = fmaxf(mt1, __shfl_xor_sync(0xffffffffu, mt1, off));
            }
            float mn0 = fmaxf(m0, mt0), mn1 = fmaxf(m1, mt1);
            float al0 = __expf(m0 - mn0), al1 = __expf(m1 - mn1);
            m0 = mn0; m1 = mn1;

            float sum0 = 0.f, sum1 = 0.f;
#pragma unroll
            for (int nt = 0; nt < 8; nt++) {
                s[nt][0] = __expf(s[nt][0] - mn0); sum0 += s[nt][0];
                s[nt][1] = __expf(s[nt][1] - mn0); sum0 += s[nt][1];
                s[nt][2] = __expf(s[nt][2] - mn1); sum1 += s[nt][2];
                s[nt][3] = __expf(s[nt][3] - mn1); sum1 += s[nt][3];
            }
#pragma unroll
            for (int off = 1; off <= 2; off <<= 1) {
                sum0 += __shfl_xor_sync(0xffffffffu, sum0, off);
                sum1 += __shfl_xor_sync(0xffffffffu, sum1, off);
            }
            l0 = l0 * al0 + sum0;
            l1 = l1 * al1 + sum1;
#pragma unroll
            for (int nt = 0; nt < 16; nt++) {
                O[nt][0] *= al0; O[nt][1] *= al0;
                O[nt][2] *= al1; O[nt][3] *= al1;
            }

            // ---- O += P V  (P packed in registers; no smem round-trip) ----
#pragma unroll
            for (int c = 0; c < 4; c++) {
                uint32_t pa[4];
                pa[0] = pk_h2(s[2 * c][0],     s[2 * c][1]);
                pa[1] = pk_h2(s[2 * c][2],     s[2 * c][3]);
                pa[2] = pk_h2(s[2 * c + 1][0], s[2 * c + 1][1]);
                pa[3] = pk_h2(s[2 * c + 1][2], s[2 * c + 1][3]);
#pragma unroll
                for (int nt = 0; nt < 16; nt++) {
                    uint32_t vb[2];
                    const uint32_t* vbp = &Vs[(nt * 8 + lr) * 36 + c * 8 + lk];
                    vb[0] = vbp[0];
                    vb[1] = vbp[4];
                    MMA_F16(O[nt], pa, vb);
                }
            }
        }
        __syncthreads();
    }

    // ---- epilogue ----
    float inv0 = 1.0f / l0, inv1 = 1.0f / l1;
    size_t r0base = (size_t)(b * T_ + q0 + w * 16 + lr) * D_ + h * HD_;
    size_t r1base = (size_t)(b * T_ + q0 + w * 16 + lr + 8) * D_ + h * HD_;
#pragma unroll
    for (int nt = 0; nt < 16; nt++) {
        float2 c0 = { O[nt][0] * inv0, O[nt][1] * inv0 };
        float2 c1 = { O[nt][2] * inv1, O[nt][3] * inv1 };
        *(float2*)&o[r0base + nt * 8 + 2 * lk] = c0;
        *(float2*)&o[r1base + nt * 8 + 2 * lk] = c1;
    }
}

// ---------------------------------------------------------------------------
// Launcher
// ---------------------------------------------------------------------------
extern "C" void kernel_launch(void* const* d_in, const int* in_sizes, int n_in,
                              void* d_out, int out_size)
{
    const float* x    = (const float*)d_in[0];
    const float* cosT = (const float*)d_in[1];
    const float* sinT = (const float*)d_in[2];
    const float* Wq   = (const float*)d_in[3];
    const float* Wk   = (const float*)d_in[4];
    const float* Wv   = (const float*)d_in[5];
    const float* Wo   = (const float*)d_in[6];
    float* out = (float*)d_out;

    float *gq, *gk, *gv, *gattn;
    cudaGetSymbolAddress((void**)&gq,    g_q);
    cudaGetSymbolAddress((void**)&gk,    g_k);
    cudaGetSymbolAddress((void**)&gv,    g_v);
    cudaGetSymbolAddress((void**)&gattn, g_attn);

    cudaFuncSetAttribute(attn_f16_kernel, cudaFuncAttributeMaxDynamicSharedMemorySize,
                         ATTN_SMEM_BYTES);
    cudaFuncSetAttribute(gemm_nt_f16_kernel,
                         cudaFuncAttributeMaxDynamicSharedMemorySize,
                         GEMM_SMEM_BYTES);

    dim3 blk(256);
    dim3 gq_grid(D_ / 128, M_ / 128);
    dim3 gkv_grid(KVD_ / 128, M_ / 128);

    gemm_nt_f16_kernel<<<gq_grid,  blk, GEMM_SMEM_BYTES>>>(x, Wq, gq, M_, D_,   D_);
    gemm_nt_f16_kernel<<<gkv_grid, blk, GEMM_SMEM_BYTES>>>(x, Wk, gk, M_, KVD_, D_);
    gemm_nt_f16_kernel<<<gkv_grid, blk, GEMM_SMEM_BYTES>>>(x, Wv, gv, M_, KVD_, D_);

    rope_kernel<<<M_, blk>>>(gq, gk, cosT, sinT);

    dim3 ga(T_ / 128, H_, B_);
    attn_f16_kernel<<<ga, blk, ATTN_SMEM_BYTES>>>(gq, gk, gv, gattn);

    gemm_nt_f16_kernel<<<gq_grid, blk, GEMM_SMEM_BYTES>>>(gattn, Wo, out, M_, D_, D_);
}

// round 8
// speedup vs baseline: 4.3265x; 1.2240x over previous
#include <cuda_runtime.h>
#include <cuda_fp16.h>
#include <math_constants.h>
#include <stdint.h>

// Problem constants
#define B_   2
#define T_   2048
#define D_   2048
#define H_   16
#define HKV_ 4
#define HD_  128
#define G_   (H_ / HKV_)      // 4
#define M_   (B_ * T_)        // 4096
#define KVD_ (HKV_ * HD_)     // 512

// ---------------------------------------------------------------------------
// Scratch (device globals; no allocation allowed)
// ---------------------------------------------------------------------------
__device__ float g_q[(size_t)M_ * D_];     // 32 MB
__device__ float g_k[(size_t)M_ * KVD_];   //  8 MB
__device__ float g_v[(size_t)M_ * KVD_];   //  8 MB
__device__ float g_attn[(size_t)M_ * D_];  // 32 MB

// ---------------------------------------------------------------------------
// Helpers
// ---------------------------------------------------------------------------
__device__ __forceinline__ uint32_t pk_h2(float lo, float hi) {
    half2 h = __floats2half2_rn(lo, hi);
    return *(uint32_t*)&h;
}

__device__ __forceinline__ uint32_t smem_u32(const void* p) {
    uint32_t a;
    asm("{ .reg .u64 t; cvta.to.shared.u64 t, %1; cvt.u32.u64 %0, t; }"
        : "=r"(a) : "l"(p));
    return a;
}

#define MMA_F16(c, a, b)                                                      \
    asm volatile(                                                             \
        "mma.sync.aligned.m16n8k16.row.col.f32.f16.f16.f32 "                  \
        "{%0,%1,%2,%3},{%4,%5,%6,%7},{%8,%9},{%0,%1,%2,%3};"                  \
        : "+f"((c)[0]), "+f"((c)[1]), "+f"((c)[2]), "+f"((c)[3])              \
        : "r"((a)[0]), "r"((a)[1]), "r"((a)[2]), "r"((a)[3]),                 \
          "r"((b)[0]), "r"((b)[1]))

#define LDSM_X4(r0, r1, r2, r3, addr)                                         \
    asm volatile(                                                             \
        "ldmatrix.sync.aligned.m8n8.x4.shared.b16 {%0,%1,%2,%3}, [%4];"       \
        : "=r"(r0), "=r"(r1), "=r"(r2), "=r"(r3) : "r"(addr))

// ---------------------------------------------------------------------------
// fp16 tensor-core GEMM: C[M,N] = A[M,K] @ Bm[N,K]^T
// BM=BN=128, BK=32 (floats), 256 threads (8 warps 2x4), warp tile 64x32.
// Smem half2 words, row stride 20 (16 data + 4 pad) — ldmatrix conflict-free
// (row offsets mod 32 banks: 0,20,8,28,16,4,24,12). Fragments via
// ldmatrix.x4. Double-buffered with register prefetch.
// ---------------------------------------------------------------------------
#define HSTRIDE 20
#define HROW_BYTES (HSTRIDE * 4)                 // 80
#define HTILE_WORDS (128 * HSTRIDE)              // 2560 u32 per tile
#define HTILE_BYTES (HTILE_WORDS * 4)            // 10240
#define GEMM_SMEM_BYTES (4 * HTILE_BYTES)        // 40960 B

__global__ __launch_bounds__(256) void gemm_nt_f16_kernel(
    const float* __restrict__ A, const float* __restrict__ Bm,
    float* __restrict__ C, int M, int N, int K)
{
    extern __shared__ uint32_t smw[];
    uint32_t* As[2] = { smw,                   smw + HTILE_WORDS };
    uint32_t* Bs[2] = { smw + 2 * HTILE_WORDS, smw + 3 * HTILE_WORDS };
    const uint32_t smBase = smem_u32(smw);

    const int tid  = threadIdx.x;
    const int lane = tid & 31;
    const int warp = tid >> 5;
    const int row0 = blockIdx.y * 128;
    const int col0 = blockIdx.x * 128;
    const int wm   = (warp >> 2) * 64;
    const int wn   = (warp & 3) * 32;
    const int lk   = lane & 3;
    const int lr   = lane >> 2;

    // ldmatrix per-lane address offsets (bytes)
    const uint32_t aoff = (uint32_t)(lane & 15) * HROW_BYTES + (uint32_t)(lane >> 4) * 16;
    const uint32_t boff = ((uint32_t)((lane >> 4) * 8 + (lane & 7))) * HROW_BYTES
                        + (uint32_t)((lane >> 3) & 1) * 16;

    int mL[4], kqL[4], kwL[4];
#pragma unroll
    for (int t = 0; t < 4; t++) {
        int idx = tid + 256 * t;
        mL[t]  = idx >> 3;
        kqL[t] = (idx & 7) << 2;
        kwL[t] = (idx & 7) << 1;
    }

    float c[4][4][4];
#pragma unroll
    for (int mi = 0; mi < 4; mi++)
#pragma unroll
        for (int ni = 0; ni < 4; ni++)
#pragma unroll
            for (int r = 0; r < 4; r++) c[mi][ni][r] = 0.f;

    const int niter = K >> 5;
    float4 pa[4], pb[4];

#pragma unroll
    for (int t = 0; t < 4; t++) {
        pa[t] = *(const float4*)&A [(size_t)(row0 + mL[t]) * K + kqL[t]];
        pb[t] = *(const float4*)&Bm[(size_t)(col0 + mL[t]) * K + kqL[t]];
    }
#pragma unroll
    for (int t = 0; t < 4; t++) {
        uint2 wa = { pk_h2(pa[t].x, pa[t].y), pk_h2(pa[t].z, pa[t].w) };
        *(uint2*)&As[0][mL[t] * HSTRIDE + kwL[t]] = wa;
        uint2 wb = { pk_h2(pb[t].x, pb[t].y), pk_h2(pb[t].z, pb[t].w) };
        *(uint2*)&Bs[0][mL[t] * HSTRIDE + kwL[t]] = wb;
    }
    __syncthreads();

    for (int it = 0; it < niter; ++it) {
        const int cur = it & 1;
        if (it + 1 < niter) {
            const int k0 = (it + 1) << 5;
#pragma unroll
            for (int t = 0; t < 4; t++) {
                pa[t] = *(const float4*)&A [(size_t)(row0 + mL[t]) * K + k0 + kqL[t]];
                pb[t] = *(const float4*)&Bm[(size_t)(col0 + mL[t]) * K + k0 + kqL[t]];
            }
        }

        const uint32_t aB = smBase + (uint32_t)cur * HTILE_BYTES + aoff;
        const uint32_t bB = smBase + (uint32_t)(2 + cur) * HTILE_BYTES + boff;
#pragma unroll
        for (int s = 0; s < 2; s++) {
            const uint32_t so = (uint32_t)s * 32;    // 8 words
            uint32_t af[4][4], bf[4][2];
#pragma unroll
            for (int mi = 0; mi < 4; mi++)
                LDSM_X4(af[mi][0], af[mi][1], af[mi][2], af[mi][3],
                        aB + (uint32_t)(wm + 16 * mi) * HROW_BYTES + so);
#pragma unroll
            for (int p = 0; p < 2; p++)
                LDSM_X4(bf[2 * p][0], bf[2 * p][1], bf[2 * p + 1][0], bf[2 * p + 1][1],
                        bB + (uint32_t)(wn + 16 * p) * HROW_BYTES + so);
#pragma unroll
            for (int mi = 0; mi < 4; mi++)
#pragma unroll
                for (int ni = 0; ni < 4; ni++)
                    MMA_F16(c[mi][ni], af[mi], bf[ni]);
        }

        if (it + 1 < niter) {
            const int nb = (it + 1) & 1;
#pragma unroll
            for (int t = 0; t < 4; t++) {
                uint2 wa = { pk_h2(pa[t].x, pa[t].y), pk_h2(pa[t].z, pa[t].w) };
                *(uint2*)&As[nb][mL[t] * HSTRIDE + kwL[t]] = wa;
                uint2 wb = { pk_h2(pb[t].x, pb[t].y), pk_h2(pb[t].z, pb[t].w) };
                *(uint2*)&Bs[nb][mL[t] * HSTRIDE + kwL[t]] = wb;
            }
        }
        __syncthreads();
    }

#pragma unroll
    for (int mi = 0; mi < 4; mi++) {
#pragma unroll
        for (int ni = 0; ni < 4; ni++) {
            int r  = row0 + wm + 16 * mi + lr;
            int cc = col0 + wn + 8 * ni + 2 * lk;
            C[(size_t)r * N + cc]           = c[mi][ni][0];
            C[(size_t)r * N + cc + 1]       = c[mi][ni][1];
            C[(size_t)(r + 8) * N + cc]     = c[mi][ni][2];
            C[(size_t)(r + 8) * N + cc + 1] = c[mi][ni][3];
        }
    }
}

// ---------------------------------------------------------------------------
// RoPE (unchanged)
// ---------------------------------------------------------------------------
__global__ __launch_bounds__(256) void rope_kernel(
    float* __restrict__ q, float* __restrict__ k,
    const float* __restrict__ cosT, const float* __restrict__ sinT)
{
    const int bt  = blockIdx.x;
    const int t   = bt & (T_ - 1);
    const int tid = threadIdx.x;
    const float* cr = cosT + (size_t)t * HD_;
    const float* sr = sinT + (size_t)t * HD_;

    float* qrow = q + (size_t)bt * D_;
    for (int p = tid; p < H_ * 64; p += 256) {
        int h = p >> 6, i = p & 63;
        float* base = qrow + h * HD_;
        float q1 = base[i], q2 = base[i + 64];
        base[i]      = q1 * cr[i]      - q2 * sr[i];
        base[i + 64] = q2 * cr[i + 64] + q1 * sr[i + 64];
    }
    float* krow = k + (size_t)bt * KVD_;
    for (int p = tid; p < HKV_ * 64; p += 256) {
        int h = p >> 6, i = p & 63;
        float* base = krow + h * HD_;
        float k1 = base[i], k2 = base[i + 64];
        base[i]      = k1 * cr[i]      - k2 * sr[i];
        base[i + 64] = k2 * cr[i + 64] + k1 * sr[i + 64];
    }
}

// ---------------------------------------------------------------------------
// fp16 tensor-core causal flash attention (m16n8k16 + ldmatrix).
// Grid: (T/128, H, B). Block: 256 threads = 8 warps; warp w owns q-rows
// [w*16, w*16+16). BQ=128, BK=64, HD=128.
// Smem (u32 words): Ks[64][68] half2 d-packed @0, Vs[128][36] half2
// key-packed (transposed) @4352. Q staging [128][68] aliases both.
// Row strides 68/36 words are ldmatrix conflict-free (mod-32 = 4k pattern).
// P stays in registers (S C-frag == PV A-frag layout after half2 pack).
// ---------------------------------------------------------------------------
#define AT_VS_OFF 4352
#define AT_WORDS  8960
#define ATTN_SMEM_BYTES (AT_WORDS * 4)   // 35840
#define KS_ROW_BYTES 272                 // 68 words
#define VS_ROW_BYTES 144                 // 36 words

__global__ __launch_bounds__(256) void attn_f16_kernel(
    const float* __restrict__ q, const float* __restrict__ k,
    const float* __restrict__ v, float* __restrict__ o)
{
    extern __shared__ uint32_t sw[];
    uint32_t* Ks = sw;                 // [64][68]
    uint32_t* Vs = sw + AT_VS_OFF;     // [128][36]
    uint32_t* Qs = sw;                 // staging [128][68], aliases Ks+Vs

    const int qt  = blockIdx.x;
    const int h   = blockIdx.y;
    const int b   = blockIdx.z;
    const int kvh = h >> 2;
    const int q0  = qt * 128;
    const int tid  = threadIdx.x;
    const int lane = tid & 31;
    const int w    = tid >> 5;
    const int lr   = lane >> 2;
    const int lk   = lane & 3;
    const float scale = 0.08838834764831845f;   // 1/sqrt(128)

    const uint32_t KsU32 = smem_u32(sw);
    const uint32_t VsU32 = KsU32 + AT_VS_OFF * 4;
    // b-operand ldmatrix lane offset: row=(lane>>4)*8+(lane&7), colsel=(lane>>3)&1
    const uint32_t brow   = (uint32_t)((lane >> 4) * 8 + (lane & 7));
    const uint32_t bcol16 = (uint32_t)((lane >> 3) & 1) * 16;

    // ---- stage Q (scaled, fp16) and pull A-fragments into registers ----
    {
        int row = tid >> 1;
        int d0  = (tid & 1) * 64;
        const float* src = q + (size_t)(b * T_ + q0 + row) * D_ + h * HD_ + d0;
#pragma unroll
        for (int j = 0; j < 64; j += 4) {
            float4 a = *(const float4*)(src + j);
            uint2 wv = { pk_h2(a.x * scale, a.y * scale),
                         pk_h2(a.z * scale, a.w * scale) };
            *(uint2*)&Qs[row * 68 + ((d0 + j) >> 1)] = wv;
        }
    }
    __syncthreads();

    uint32_t aQ[8][4];
#pragma unroll
    for (int c = 0; c < 8; c++) {
        const uint32_t* base = &Qs[(w * 16 + lr) * 68 + c * 8 + lk];
        aQ[c][0] = base[0];
        aQ[c][1] = base[8 * 68];
        aQ[c][2] = base[4];
        aQ[c][3] = base[8 * 68 + 4];
    }
    __syncthreads();

    float O[16][4];
#pragma unroll
    for (int nt = 0; nt < 16; nt++)
#pragma unroll
        for (int r = 0; r < 4; r++) O[nt][r] = 0.f;
    float m0 = -CUDART_INF_F, m1 = -CUDART_INF_F, l0 = 0.f, l1 = 0.f;

    const int row0g = q0 + w * 16 + lr;
    const int nkt = 2 * qt + 2;

    for (int kt = 0; kt < nkt; kt++) {
        const int k0 = kt * 64;
        // ---- load K (half2, d-packed) and V transposed (half2, key-packed) ----
        {
            int row = tid >> 2;                 // key 0..63
            int d0  = (tid & 3) * 32;
            const float* ksrc = k + (size_t)(b * T_ + k0 + row) * KVD_ + kvh * HD_ + d0;
            const float* vsrc = v + (size_t)(b * T_ + k0 + row) * KVD_ + kvh * HD_ + d0;
            __half* Vh = (__half*)Vs;           // rows = d, stride 72 halves
#pragma unroll
            for (int j = 0; j < 32; j += 4) {
                float4 a = *(const float4*)(ksrc + j);
                uint2 wa = { pk_h2(a.x, a.y), pk_h2(a.z, a.w) };
                *(uint2*)&Ks[row * 68 + ((d0 + j) >> 1)] = wa;
                float4 bb = *(const float4*)(vsrc + j);
                Vh[(d0 + j + 0) * 72 + row] = __float2half_rn(bb.x);
                Vh[(d0 + j + 1) * 72 + row] = __float2half_rn(bb.y);
                Vh[(d0 + j + 2) * 72 + row] = __float2half_rn(bb.z);
                Vh[(d0 + j + 3) * 72 + row] = __float2half_rn(bb.w);
            }
        }
        __syncthreads();

        const bool active = (k0 <= q0 + w * 16 + 15);   // warp-uniform
        if (active) {
            // ---- S = Q K^T ----
            float s[8][4];
#pragma unroll
            for (int nt = 0; nt < 8; nt++)
#pragma unroll
                for (int r = 0; r < 4; r++) s[nt][r] = 0.f;

#pragma unroll
            for (int c = 0; c < 8; c++) {
                uint32_t bf[8][2];
#pragma unroll
                for (int p = 0; p < 4; p++)
                    LDSM_X4(bf[2 * p][0], bf[2 * p][1], bf[2 * p + 1][0], bf[2 * p + 1][1],
                            KsU32 + (uint32_t)(p * 16 + brow) * KS_ROW_BYTES
                                  + (uint32_t)c * 32 + bcol16);
#pragma unroll
                for (int nt = 0; nt < 8; nt++)
                    MMA_F16(s[nt], aQ[c], bf[nt]);
            }

            // ---- causal mask (only near diagonal) ----
            if (k0 + 63 > q0 + w * 16) {
#pragma unroll
                for (int nt = 0; nt < 8; nt++) {
                    int c0 = k0 + nt * 8 + 2 * lk;
                    if (c0     > row0g)     s[nt][0] = -CUDART_INF_F;
                    if (c0 + 1 > row0g)     s[nt][1] = -CUDART_INF_F;
                    if (c0     > row0g + 8) s[nt][2] = -CUDART_INF_F;
                    if (c0 + 1 > row0g + 8) s[nt][3] = -CUDART_INF_F;
                }
            }

            // ---- online softmax on fragment rows ----
            float mt0 = -CUDART_INF_F, mt1 = -CUDART_INF_F;
#pragma unroll
            for (int nt = 0; nt < 8; nt++) {
                mt0 = fmaxf(mt0, fmaxf(s[nt][0], s[nt][1]));
                mt1 = fmaxf(mt1, fmaxf(s[nt][2], s[nt][3]));
            }
#pragma unroll
            for (int off = 1; off <= 2; off <<= 1) {
                mt0 = fmaxf(mt0, __shfl_xor_sync(0xffffffffu, mt0, off));
                mt1 = fmaxf(mt1, __shfl_xor_sync(0xffffffffu, mt1, off));
            }
            float mn0 = fmaxf(m0, mt0), mn1 = fmaxf(m1, mt1);
            float al0 = __expf(m0 - mn0), al1 = __expf(m1 - mn1);
            m0 = mn0; m1 = mn1;

            float sum0 = 0.f, sum1 = 0.f;
#pragma unroll
            for (int nt = 0; nt < 8; nt++) {
                s[nt][0] = __expf(s[nt][0] - mn0); sum0 += s[nt][0];
                s[nt][1] = __expf(s[nt][1] - mn0); sum0 += s[nt][1];
                s[nt][2] = __expf(s[nt][2] - mn1); sum1 += s[nt][2];
                s[nt][3] = __expf(s[nt][3] - mn1); sum1 += s[nt][3];
            }
#pragma unroll
            for (int off = 1; off <= 2; off <<= 1) {
                sum0 += __shfl_xor_sync(0xffffffffu, sum0, off);
                sum1 += __shfl_xor_sync(0xffffffffu, sum1, off);
            }
            l0 = l0 * al0 + sum0;
            l1 = l1 * al1 + sum1;
#pragma unroll
            for (int nt = 0; nt < 16; nt++) {
                O[nt][0] *= al0; O[nt][1] *= al0;
                O[nt][2] *= al1; O[nt][3] *= al1;
            }

            // ---- O += P V  (P packed in registers; V frags via ldmatrix) ----
#pragma unroll
            for (int c = 0; c < 4; c++) {
                uint32_t pa[4];
                pa[0] = pk_h2(s[2 * c][0],     s[2 * c][1]);
                pa[1] = pk_h2(s[2 * c][2],     s[2 * c][3]);
                pa[2] = pk_h2(s[2 * c + 1][0], s[2 * c + 1][1]);
                pa[3] = pk_h2(s[2 * c + 1][2], s[2 * c + 1][3]);
#pragma unroll
                for (int p = 0; p < 8; p++) {
                    uint32_t vb[2][2];
                    LDSM_X4(vb[0][0], vb[0][1], vb[1][0], vb[1][1],
                            VsU32 + (uint32_t)(p * 16 + brow) * VS_ROW_BYTES
                                  + (uint32_t)c * 32 + bcol16);
                    MMA_F16(O[2 * p],     pa, vb[0]);
                    MMA_F16(O[2 * p + 1], pa, vb[1]);
                }
            }
        }
        __syncthreads();
    }

    // ---- epilogue ----
    float inv0 = 1.0f / l0, inv1 = 1.0f / l1;
    size_t r0base = (size_t)(b * T_ + q0 + w * 16 + lr) * D_ + h * HD_;
    size_t r1base = (size_t)(b * T_ + q0 + w * 16 + lr + 8) * D_ + h * HD_;
#pragma unroll
    for (int nt = 0; nt < 16; nt++) {
        float2 c0 = { O[nt][0] * inv0, O[nt][1] * inv0 };
        float2 c1 = { O[nt][2] * inv1, O[nt][3] * inv1 };
        *(float2*)&o[r0base + nt * 8 + 2 * lk] = c0;
        *(float2*)&o[r1base + nt * 8 + 2 * lk] = c1;
    }
}

// ---------------------------------------------------------------------------
// Launcher
// ---------------------------------------------------------------------------
extern "C" void kernel_launch(void* const* d_in, const int* in_sizes, int n_in,
                              void* d_out, int out_size)
{
    const float* x    = (const float*)d_in[0];
    const float* cosT = (const float*)d_in[1];
    const float* sinT = (const float*)d_in[2];
    const float* Wq   = (const float*)d_in[3];
    const float* Wk   = (const float*)d_in[4];
    const float* Wv   = (const float*)d_in[5];
    const float* Wo   = (const float*)d_in[6];
    float* out = (float*)d_out;

    float *gq, *gk, *gv, *gattn;
    cudaGetSymbolAddress((void**)&gq,    g_q);
    cudaGetSymbolAddress((void**)&gk,    g_k);
    cudaGetSymbolAddress((void**)&gv,    g_v);
    cudaGetSymbolAddress((void**)&gattn, g_attn);

    cudaFuncSetAttribute(attn_f16_kernel, cudaFuncAttributeMaxDynamicSharedMemorySize,
                         ATTN_SMEM_BYTES);
    cudaFuncSetAttribute(gemm_nt_f16_kernel,
                         cudaFuncAttributeMaxDynamicSharedMemorySize,
                         GEMM_SMEM_BYTES);

    dim3 blk(256);
    dim3 gq_grid(D_ / 128, M_ / 128);
    dim3 gkv_grid(KVD_ / 128, M_ / 128);

    gemm_nt_f16_kernel<<<gq_grid,  blk, GEMM_SMEM_BYTES>>>(x, Wq, gq, M_, D_,   D_);
    gemm_nt_f16_kernel<<<gkv_grid, blk, GEMM_SMEM_BYTES>>>(x, Wk, gk, M_, KVD_, D_);
    gemm_nt_f16_kernel<<<gkv_grid, blk, GEMM_SMEM_BYTES>>>(x, Wv, gv, M_, KVD_, D_);

    rope_kernel<<<M_, blk>>>(gq, gk, cosT, sinT);

    dim3 ga(T_ / 128, H_, B_);
    attn_f16_kernel<<<ga, blk, ATTN_SMEM_BYTES>>>(gq, gk, gv, gattn);

    gemm_nt_f16_kernel<<<gq_grid, blk, GEMM_SMEM_BYTES>>>(gattn, Wo, out, M_, D_, D_);
}

// round 9
// speedup vs baseline: 6.1673x; 1.4255x over previous
#include <cuda_runtime.h>
#include <cuda_fp16.h>
#include <math_constants.h>
#include <stdint.h>

// Problem constants
#define B_   2
#define T_   2048
#define D_   2048
#define H_   16
#define HKV_ 4
#define HD_  128
#define G_   (H_ / HKV_)      // 4
#define M_   (B_ * T_)        // 4096
#define KVD_ (HKV_ * HD_)     // 512

// ---------------------------------------------------------------------------
// Scratch (device globals; no allocation allowed) — all fp16 now
// ---------------------------------------------------------------------------
__device__ __half g_xh[(size_t)M_ * D_];     // 16 MB
__device__ __half g_wqh[(size_t)D_ * D_];    //  8 MB
__device__ __half g_wkh[(size_t)KVD_ * D_];  //  2 MB
__device__ __half g_wvh[(size_t)KVD_ * D_];  //  2 MB
__device__ __half g_woh[(size_t)D_ * D_];    //  8 MB
__device__ __half g_q[(size_t)M_ * D_];      // 16 MB
__device__ __half g_k[(size_t)M_ * KVD_];    //  4 MB
__device__ __half g_v[(size_t)M_ * KVD_];    //  4 MB
__device__ __half g_attn[(size_t)M_ * D_];   // 16 MB

// ---------------------------------------------------------------------------
// Helpers
// ---------------------------------------------------------------------------
__device__ __forceinline__ uint32_t pk_h2(float lo, float hi) {
    half2 h = __floats2half2_rn(lo, hi);
    return *(uint32_t*)&h;
}

__device__ __forceinline__ uint32_t smem_u32(const void* p) {
    uint32_t a;
    asm("{ .reg .u64 t; cvta.to.shared.u64 t, %1; cvt.u32.u64 %0, t; }"
        : "=r"(a) : "l"(p));
    return a;
}

#define MMA_F16(c, a, b)                                                      \
    asm volatile(                                                             \
        "mma.sync.aligned.m16n8k16.row.col.f32.f16.f16.f32 "                  \
        "{%0,%1,%2,%3},{%4,%5,%6,%7},{%8,%9},{%0,%1,%2,%3};"                  \
        : "+f"((c)[0]), "+f"((c)[1]), "+f"((c)[2]), "+f"((c)[3])              \
        : "r"((a)[0]), "r"((a)[1]), "r"((a)[2]), "r"((a)[3]),                 \
          "r"((b)[0]), "r"((b)[1]))

#define LDSM_X4(r0, r1, r2, r3, addr)                                         \
    asm volatile(                                                             \
        "ldmatrix.sync.aligned.m8n8.x4.shared.b16 {%0,%1,%2,%3}, [%4];"       \
        : "=r"(r0), "=r"(r1), "=r"(r2), "=r"(r3) : "r"(addr))

#define LDSM_X4_T(r0, r1, r2, r3, addr)                                       \
    asm volatile(                                                             \
        "ldmatrix.sync.aligned.m8n8.x4.trans.shared.b16 {%0,%1,%2,%3}, [%4];" \
        : "=r"(r0), "=r"(r1), "=r"(r2), "=r"(r3) : "r"(addr))

// ---------------------------------------------------------------------------
// fp32 -> fp16 conversion (8 floats / thread)
// ---------------------------------------------------------------------------
__global__ __launch_bounds__(256) void f2h_kernel(
    const float* __restrict__ in, __half* __restrict__ out, int n)
{
    int i = (blockIdx.x * 256 + threadIdx.x) * 8;
    if (i >= n) return;
    float4 a = *(const float4*)(in + i);
    float4 b = *(const float4*)(in + i + 4);
    uint4 o = { pk_h2(a.x, a.y), pk_h2(a.z, a.w),
                pk_h2(b.x, b.y), pk_h2(b.z, b.w) };
    *(uint4*)(out + i) = o;
}

// ---------------------------------------------------------------------------
// fp16 tensor-core GEMM: C[M,N] = A[M,K] @ Bm[N,K]^T  (half inputs)
// BM=BN=128, BK=32, 256 threads (8 warps 2x4), warp tile 64x32.
// Smem row stride 20 words (16 data + 4 pad), ldmatrix conflict-free.
// Half or float output (Ch xor Cf non-null).
// ---------------------------------------------------------------------------
#define HSTRIDE 20
#define HROW_BYTES (HSTRIDE * 4)                 // 80
#define HTILE_WORDS (128 * HSTRIDE)              // 2560 u32 per tile
#define HTILE_BYTES (HTILE_WORDS * 4)            // 10240
#define GEMM_SMEM_BYTES (4 * HTILE_BYTES)        // 40960 B

__global__ __launch_bounds__(256) void gemm_nt_h_kernel(
    const __half* __restrict__ A, const __half* __restrict__ Bm,
    __half* __restrict__ Ch, float* __restrict__ Cf, int M, int N, int K)
{
    extern __shared__ uint32_t smw[];
    uint32_t* As[2] = { smw,                   smw + HTILE_WORDS };
    uint32_t* Bs[2] = { smw + 2 * HTILE_WORDS, smw + 3 * HTILE_WORDS };
    const uint32_t smBase = smem_u32(smw);

    const int tid  = threadIdx.x;
    const int lane = tid & 31;
    const int warp = tid >> 5;
    const int row0 = blockIdx.y * 128;
    const int col0 = blockIdx.x * 128;
    const int wm   = (warp >> 2) * 64;
    const int wn   = (warp & 3) * 32;
    const int lk   = lane & 3;
    const int lr   = lane >> 2;

    const uint32_t aoff = (uint32_t)(lane & 15) * HROW_BYTES + (uint32_t)(lane >> 4) * 16;
    const uint32_t boff = ((uint32_t)((lane >> 4) * 8 + (lane & 7))) * HROW_BYTES
                        + (uint32_t)((lane >> 3) & 1) * 16;

    // global-load coords: idx -> m = idx>>2, half col = (idx&3)*8
    int mL[2], hcL[2], wL[2];
#pragma unroll
    for (int t = 0; t < 2; t++) {
        int idx = tid + 256 * t;
        mL[t]  = idx >> 2;
        hcL[t] = (idx & 3) << 3;    // half index 0,8,16,24
        wL[t]  = (idx & 3) << 2;    // word index 0,4,8,12
    }

    float c[4][4][4];
#pragma unroll
    for (int mi = 0; mi < 4; mi++)
#pragma unroll
        for (int ni = 0; ni < 4; ni++)
#pragma unroll
            for (int r = 0; r < 4; r++) c[mi][ni][r] = 0.f;

    const int niter = K >> 5;
    uint4 ra[2], rb[2];

#pragma unroll
    for (int t = 0; t < 2; t++) {
        ra[t] = *(const uint4*)&A [(size_t)(row0 + mL[t]) * K + hcL[t]];
        rb[t] = *(const uint4*)&Bm[(size_t)(col0 + mL[t]) * K + hcL[t]];
    }
#pragma unroll
    for (int t = 0; t < 2; t++) {
        *(uint4*)&As[0][mL[t] * HSTRIDE + wL[t]] = ra[t];
        *(uint4*)&Bs[0][mL[t] * HSTRIDE + wL[t]] = rb[t];
    }
    __syncthreads();

    for (int it = 0; it < niter; ++it) {
        const int cur = it & 1;
        if (it + 1 < niter) {
            const int k0 = (it + 1) << 5;
#pragma unroll
            for (int t = 0; t < 2; t++) {
                ra[t] = *(const uint4*)&A [(size_t)(row0 + mL[t]) * K + k0 + hcL[t]];
                rb[t] = *(const uint4*)&Bm[(size_t)(col0 + mL[t]) * K + k0 + hcL[t]];
            }
        }

        const uint32_t aB = smBase + (uint32_t)cur * HTILE_BYTES + aoff;
        const uint32_t bB = smBase + (uint32_t)(2 + cur) * HTILE_BYTES + boff;
#pragma unroll
        for (int s = 0; s < 2; s++) {
            const uint32_t so = (uint32_t)s * 32;
            uint32_t af[4][4], bf[4][2];
#pragma unroll
            for (int mi = 0; mi < 4; mi++)
                LDSM_X4(af[mi][0], af[mi][1], af[mi][2], af[mi][3],
                        aB + (uint32_t)(wm + 16 * mi) * HROW_BYTES + so);
#pragma unroll
            for (int p = 0; p < 2; p++)
                LDSM_X4(bf[2 * p][0], bf[2 * p][1], bf[2 * p + 1][0], bf[2 * p + 1][1],
                        bB + (uint32_t)(wn + 16 * p) * HROW_BYTES + so);
#pragma unroll
            for (int mi = 0; mi < 4; mi++)
#pragma unroll
                for (int ni = 0; ni < 4; ni++)
                    MMA_F16(c[mi][ni], af[mi], bf[ni]);
        }

        if (it + 1 < niter) {
            const int nb = (it + 1) & 1;
#pragma unroll
            for (int t = 0; t < 2; t++) {
                *(uint4*)&As[nb][mL[t] * HSTRIDE + wL[t]] = ra[t];
                *(uint4*)&Bs[nb][mL[t] * HSTRIDE + wL[t]] = rb[t];
            }
        }
        __syncthreads();
    }

#pragma unroll
    for (int mi = 0; mi < 4; mi++) {
#pragma unroll
        for (int ni = 0; ni < 4; ni++) {
            int r  = row0 + wm + 16 * mi + lr;
            int cc = col0 + wn + 8 * ni + 2 * lk;
            if (Ch) {
                *(uint32_t*)&Ch[(size_t)r * N + cc]       = pk_h2(c[mi][ni][0], c[mi][ni][1]);
                *(uint32_t*)&Ch[(size_t)(r + 8) * N + cc] = pk_h2(c[mi][ni][2], c[mi][ni][3]);
            } else {
                C_STORE:
                Cf[(size_t)r * N + cc]           = c[mi][ni][0];
                Cf[(size_t)r * N + cc + 1]       = c[mi][ni][1];
                Cf[(size_t)(r + 8) * N + cc]     = c[mi][ni][2];
                Cf[(size_t)(r + 8) * N + cc + 1] = c[mi][ni][3];
            }
        }
    }
}

// ---------------------------------------------------------------------------
// RoPE on half buffers; folds 1/sqrt(HD) scale into Q.
// ---------------------------------------------------------------------------
__global__ __launch_bounds__(256) void rope_h_kernel(
    __half* __restrict__ q, __half* __restrict__ k,
    const float* __restrict__ cosT, const float* __restrict__ sinT)
{
    const int bt  = blockIdx.x;
    const int t   = bt & (T_ - 1);
    const int tid = threadIdx.x;
    const float scale = 0.08838834764831845f;
    const float* cr = cosT + (size_t)t * HD_;
    const float* sr = sinT + (size_t)t * HD_;

    __half* qrow = q + (size_t)bt * D_;
    for (int p = tid; p < H_ * 64; p += 256) {
        int h = p >> 6, i = p & 63;
        __half* base = qrow + h * HD_;
        float q1 = __half2float(base[i]), q2 = __half2float(base[i + 64]);
        base[i]      = __float2half_rn((q1 * cr[i]      - q2 * sr[i]) * scale);
        base[i + 64] = __float2half_rn((q2 * cr[i + 64] + q1 * sr[i + 64]) * scale);
    }
    __half* krow = k + (size_t)bt * KVD_;
    for (int p = tid; p < HKV_ * 64; p += 256) {
        int h = p >> 6, i = p & 63;
        __half* base = krow + h * HD_;
        float k1 = __half2float(base[i]), k2 = __half2float(base[i + 64]);
        base[i]      = __float2half_rn(k1 * cr[i]      - k2 * sr[i]);
        base[i + 64] = __float2half_rn(k2 * cr[i + 64] + k1 * sr[i + 64]);
    }
}

// ---------------------------------------------------------------------------
// fp16 flash attention (m16n8k16, ldmatrix + ldmatrix.trans, half I/O).
// Grid: (T/128, H, B). Block: 256 = 8 warps; warp w owns q-rows [w*16,w*16+16).
// Smem (u32 words): Ks[64][68] @0, Vs[64][68] @4352 — both key-row-major,
// d packed as half2. Q staging [128][68] aliases both. V B-frags via
// ldmatrix.trans (no transpose staging). P stays in registers.
// ---------------------------------------------------------------------------
#define AT_VS_OFF 4352
#define AT_WORDS  8704
#define ATTN_SMEM_BYTES (AT_WORDS * 4)   // 34816
#define KS_ROW_BYTES 272                 // 68 words

__global__ __launch_bounds__(256) void attn_f16_kernel(
    const __half* __restrict__ q, const __half* __restrict__ k,
    const __half* __restrict__ v, __half* __restrict__ o)
{
    extern __shared__ uint32_t sw[];
    uint32_t* Ks = sw;                 // [64][68]
    uint32_t* Vs = sw + AT_VS_OFF;     // [64][68]
    uint32_t* Qs = sw;                 // staging [128][68], aliases Ks+Vs

    const int qt  = blockIdx.x;
    const int h   = blockIdx.y;
    const int b   = blockIdx.z;
    const int kvh = h >> 2;
    const int q0  = qt * 128;
    const int tid  = threadIdx.x;
    const int lane = tid & 31;
    const int w    = tid >> 5;
    const int lr   = lane >> 2;
    const int lk   = lane & 3;

    const uint32_t KsU32 = smem_u32(sw);
    const uint32_t VsU32 = KsU32 + AT_VS_OFF * 4;
    const uint32_t brow   = (uint32_t)((lane >> 4) * 8 + (lane & 7));
    const uint32_t bcol16 = (uint32_t)((lane >> 3) & 1) * 16;
    // a-operand / trans-b ldmatrix lane offsets
    const uint32_t arow   = (uint32_t)(lane & 15);
    const uint32_t asel16 = (uint32_t)(lane >> 4) * 16;

    // ---- stage Q (half, scale pre-folded) and pull A-fragments ----
    {
        int row = tid >> 1;
        int d0  = (tid & 1) * 64;                  // halves
        const __half* src = q + (size_t)(b * T_ + q0 + row) * D_ + h * HD_ + d0;
#pragma unroll
        for (int j = 0; j < 64; j += 8)
            *(uint4*)&Qs[row * 68 + ((d0 + j) >> 1)] = *(const uint4*)(src + j);
    }
    __syncthreads();

    uint32_t aQ[8][4];
#pragma unroll
    for (int c = 0; c < 8; c++)
        LDSM_X4(aQ[c][0], aQ[c][1], aQ[c][2], aQ[c][3],
                KsU32 + (uint32_t)(w * 16 + arow) * KS_ROW_BYTES
                      + (uint32_t)c * 32 + asel16);
    __syncthreads();

    float O[16][4];
#pragma unroll
    for (int nt = 0; nt < 16; nt++)
#pragma unroll
        for (int r = 0; r < 4; r++) O[nt][r] = 0.f;
    float m0 = -CUDART_INF_F, m1 = -CUDART_INF_F, l0 = 0.f, l1 = 0.f;

    const int row0g = q0 + w * 16 + lr;
    const int nkt = 2 * qt + 2;

    for (int kt = 0; kt < nkt; kt++) {
        const int k0 = kt * 64;
        // ---- load K and V tiles (direct half copies, key-row-major) ----
        {
            int row = tid >> 2;                 // key 0..63
            int d0  = (tid & 3) * 32;           // halves
            const __half* ksrc = k + (size_t)(b * T_ + k0 + row) * KVD_ + kvh * HD_ + d0;
            const __half* vsrc = v + (size_t)(b * T_ + k0 + row) * KVD_ + kvh * HD_ + d0;
            const int wbase = row * 68 + (d0 >> 1);
#pragma unroll
            for (int j = 0; j < 4; j++) {
                *(uint4*)&Ks[wbase + 4 * j] = *(const uint4*)(ksrc + 8 * j);
                *(uint4*)&Vs[wbase + 4 * j] = *(const uint4*)(vsrc + 8 * j);
            }
        }
        __syncthreads();

        const bool active = (k0 <= q0 + w * 16 + 15);   // warp-uniform
        if (active) {
            // ---- S = Q K^T ----
            float s[8][4];
#pragma unroll
            for (int nt = 0; nt < 8; nt++)
#pragma unroll
                for (int r = 0; r < 4; r++) s[nt][r] = 0.f;

#pragma unroll
            for (int c = 0; c < 8; c++) {
                uint32_t bf[8][2];
#pragma unroll
                for (int p = 0; p < 4; p++)
                    LDSM_X4(bf[2 * p][0], bf[2 * p][1], bf[2 * p + 1][0], bf[2 * p + 1][1],
                            KsU32 + (uint32_t)(p * 16 + brow) * KS_ROW_BYTES
                                  + (uint32_t)c * 32 + bcol16);
#pragma unroll
                for (int nt = 0; nt < 8; nt++)
                    MMA_F16(s[nt], aQ[c], bf[nt]);
            }

            // ---- causal mask ----
            if (k0 + 63 > q0 + w * 16) {
#pragma unroll
                for (int nt = 0; nt < 8; nt++) {
                    int c0 = k0 + nt * 8 + 2 * lk;
                    if (c0     > row0g)     s[nt][0] = -CUDART_INF_F;
                    if (c0 + 1 > row0g)     s[nt][1] = -CUDART_INF_F;
                    if (c0     > row0g + 8) s[nt][2] = -CUDART_INF_F;
                    if (c0 + 1 > row0g + 8) s[nt][3] = -CUDART_INF_F;
                }
            }

            // ---- online softmax ----
            float mt0 = -CUDART_INF_F, mt1 = -CUDART_INF_F;
#pragma unroll
            for (int nt = 0; nt < 8; nt++) {
                mt0 = fmaxf(mt0, fmaxf(s[nt][0], s[nt][1]));
                mt1 = fmaxf(mt1, fmaxf(s[nt][2], s[nt][3]));
            }
#pragma unroll
            for (int off = 1; off <= 2; off <<= 1) {
                mt0 = fmaxf(mt0, __shfl_xor_sync(0xffffffffu, mt0, off));
                mt1 = fmaxf(mt1, __shfl_xor_sync(0xffffffffu, mt1, off));
            }
            float mn0 = fmaxf(m0, mt0), mn1 = fmaxf(m1, mt1);
            float al0 = __expf(m0 - mn0), al1 = __expf(m1 - mn1);
            m0 = mn0; m1 = mn1;

            float sum0 = 0.f, sum1 = 0.f;
#pragma unroll
            for (int nt = 0; nt < 8; nt++) {
                s[nt][0] = __expf(s[nt][0] - mn0); sum0 += s[nt][0];
                s[nt][1] = __expf(s[nt][1] - mn0); sum0 += s[nt][1];
                s[nt][2] = __expf(s[nt][2] - mn1); sum1 += s[nt][2];
                s[nt][3] = __expf(s[nt][3] - mn1); sum1 += s[nt][3];
            }
#pragma unroll
            for (int off = 1; off <= 2; off <<= 1) {
                sum0 += __shfl_xor_sync(0xffffffffu, sum0, off);
                sum1 += __shfl_xor_sync(0xffffffffu, sum1, off);
            }
            l0 = l0 * al0 + sum0;
            l1 = l1 * al1 + sum1;
#pragma unroll
            for (int nt = 0; nt < 16; nt++) {
                O[nt][0] *= al0; O[nt][1] *= al0;
                O[nt][2] *= al1; O[nt][3] *= al1;
            }

            // ---- O += P V  (P in registers; V frags via ldmatrix.trans) ----
#pragma unroll
            for (int c = 0; c < 4; c++) {
                uint32_t pa[4];
                pa[0] = pk_h2(s[2 * c][0],     s[2 * c][1]);
                pa[1] = pk_h2(s[2 * c][2],     s[2 * c][3]);
                pa[2] = pk_h2(s[2 * c + 1][0], s[2 * c + 1][1]);
                pa[3] = pk_h2(s[2 * c + 1][2], s[2 * c + 1][3]);
#pragma unroll
                for (int p = 0; p < 8; p++) {
                    uint32_t vb[2][2];
                    LDSM_X4_T(vb[0][0], vb[0][1], vb[1][0], vb[1][1],
                              VsU32 + (uint32_t)(c * 16 + arow) * KS_ROW_BYTES
                                    + (uint32_t)p * 32 + asel16);
                    MMA_F16(O[2 * p],     pa, vb[0]);
                    MMA_F16(O[2 * p + 1], pa, vb[1]);
                }
            }
        }
        __syncthreads();
    }

    // ---- epilogue (half out) ----
    float inv0 = 1.0f / l0, inv1 = 1.0f / l1;
    size_t r0base = (size_t)(b * T_ + q0 + w * 16 + lr) * D_ + h * HD_;
    size_t r1base = (size_t)(b * T_ + q0 + w * 16 + lr + 8) * D_ + h * HD_;
#pragma unroll
    for (int nt = 0; nt < 16; nt++) {
        *(uint32_t*)&o[r0base + nt * 8 + 2 * lk] = pk_h2(O[nt][0] * inv0, O[nt][1] * inv0);
        *(uint32_t*)&o[r1base + nt * 8 + 2 * lk] = pk_h2(O[nt][2] * inv1, O[nt][3] * inv1);
    }
}

// ---------------------------------------------------------------------------
// Launcher
// ---------------------------------------------------------------------------
extern "C" void kernel_launch(void* const* d_in, const int* in_sizes, int n_in,
                              void* d_out, int out_size)
{
    const float* x    = (const float*)d_in[0];
    const float* cosT = (const float*)d_in[1];
    const float* sinT = (const float*)d_in[2];
    const float* Wq   = (const float*)d_in[3];
    const float* Wk   = (const float*)d_in[4];
    const float* Wv   = (const float*)d_in[5];
    const float* Wo   = (const float*)d_in[6];
    float* out = (float*)d_out;

    __half *xh, *wqh, *wkh, *wvh, *woh, *gq, *gk, *gv, *gattn;
    cudaGetSymbolAddress((void**)&xh,    g_xh);
    cudaGetSymbolAddress((void**)&wqh,   g_wqh);
    cudaGetSymbolAddress((void**)&wkh,   g_wkh);
    cudaGetSymbolAddress((void**)&wvh,   g_wvh);
    cudaGetSymbolAddress((void**)&woh,   g_woh);
    cudaGetSymbolAddress((void**)&gq,    g_q);
    cudaGetSymbolAddress((void**)&gk,    g_k);
    cudaGetSymbolAddress((void**)&gv,    g_v);
    cudaGetSymbolAddress((void**)&gattn, g_attn);

    cudaFuncSetAttribute(attn_f16_kernel, cudaFuncAttributeMaxDynamicSharedMemorySize,
                         ATTN_SMEM_BYTES);
    cudaFuncSetAttribute(gemm_nt_h_kernel,
                         cudaFuncAttributeMaxDynamicSharedMemorySize,
                         GEMM_SMEM_BYTES);

    dim3 blk(256);
    f2h_kernel<<<M_ * D_ / 2048,   blk>>>(x,  xh,  M_ * D_);
    f2h_kernel<<<D_ * D_ / 2048,   blk>>>(Wq, wqh, D_ * D_);
    f2h_kernel<<<KVD_ * D_ / 2048, blk>>>(Wk, wkh, KVD_ * D_);
    f2h_kernel<<<KVD_ * D_ / 2048, blk>>>(Wv, wvh, KVD_ * D_);
    f2h_kernel<<<D_ * D_ / 2048,   blk>>>(Wo, woh, D_ * D_);

    dim3 gq_grid(D_ / 128, M_ / 128);
    dim3 gkv_grid(KVD_ / 128, M_ / 128);

    gemm_nt_h_kernel<<<gq_grid,  blk, GEMM_SMEM_BYTES>>>(xh, wqh, gq, nullptr, M_, D_,   D_);
    gemm_nt_h_kernel<<<gkv_grid, blk, GEMM_SMEM_BYTES>>>(xh, wkh, gk, nullptr, M_, KVD_, D_);
    gemm_nt_h_kernel<<<gkv_grid, blk, GEMM_SMEM_BYTES>>>(xh, wvh, gv, nullptr, M_, KVD_, D_);

    rope_h_kernel<<<M_, blk>>>(gq, gk, cosT, sinT);

    dim3 ga(T_ / 128, H_, B_);
    attn_f16_kernel<<<ga, blk, ATTN_SMEM_BYTES>>>(gq, gk, gv, gattn);

    gemm_nt_h_kernel<<<gq_grid, blk, GEMM_SMEM_BYTES>>>(gattn, woh, nullptr, out, M_, D_, D_);
}

// round 10
// speedup vs baseline: 6.5367x; 1.0599x over previous
#include <cuda_runtime.h>
#include <cuda_fp16.h>
#include <math_constants.h>
#include <stdint.h>

// Problem constants
#define B_   2
#define T_   2048
#define D_   2048
#define H_   16
#define HKV_ 4
#define HD_  128
#define G_   (H_ / HKV_)      // 4
#define M_   (B_ * T_)        // 4096
#define KVD_ (HKV_ * HD_)     // 512

// ---------------------------------------------------------------------------
// Scratch (device globals; no allocation allowed) — all fp16
// ---------------------------------------------------------------------------
__device__ __half g_xh[(size_t)M_ * D_];     // 16 MB
__device__ __half g_wqh[(size_t)D_ * D_];    //  8 MB
__device__ __half g_wkh[(size_t)KVD_ * D_];  //  2 MB
__device__ __half g_wvh[(size_t)KVD_ * D_];  //  2 MB
__device__ __half g_woh[(size_t)D_ * D_];    //  8 MB
__device__ __half g_q[(size_t)M_ * D_];      // 16 MB
__device__ __half g_k[(size_t)M_ * KVD_];    //  4 MB
__device__ __half g_v[(size_t)M_ * KVD_];    //  4 MB
__device__ __half g_attn[(size_t)M_ * D_];   // 16 MB

// ---------------------------------------------------------------------------
// Helpers
// ---------------------------------------------------------------------------
__device__ __forceinline__ uint32_t pk_h2(float lo, float hi) {
    half2 h = __floats2half2_rn(lo, hi);
    return *(uint32_t*)&h;
}

__device__ __forceinline__ uint32_t smem_u32(const void* p) {
    uint32_t a;
    asm("{ .reg .u64 t; cvta.to.shared.u64 t, %1; cvt.u32.u64 %0, t; }"
        : "=r"(a) : "l"(p));
    return a;
}

#define MMA_F16(c, a, b)                                                      \
    asm volatile(                                                             \
        "mma.sync.aligned.m16n8k16.row.col.f32.f16.f16.f32 "                  \
        "{%0,%1,%2,%3},{%4,%5,%6,%7},{%8,%9},{%0,%1,%2,%3};"                  \
        : "+f"((c)[0]), "+f"((c)[1]), "+f"((c)[2]), "+f"((c)[3])              \
        : "r"((a)[0]), "r"((a)[1]), "r"((a)[2]), "r"((a)[3]),                 \
          "r"((b)[0]), "r"((b)[1]))

#define LDSM_X4(r0, r1, r2, r3, addr)                                         \
    asm volatile(                                                             \
        "ldmatrix.sync.aligned.m8n8.x4.shared.b16 {%0,%1,%2,%3}, [%4];"       \
        : "=r"(r0), "=r"(r1), "=r"(r2), "=r"(r3) : "r"(addr))

#define LDSM_X4_T(r0, r1, r2, r3, addr)                                       \
    asm volatile(                                                             \
        "ldmatrix.sync.aligned.m8n8.x4.trans.shared.b16 {%0,%1,%2,%3}, [%4];" \
        : "=r"(r0), "=r"(r1), "=r"(r2), "=r"(r3) : "r"(addr))

#define CP_ASYNC16(dst, src)                                                  \
    asm volatile("cp.async.cg.shared.global [%0], [%1], 16;"                  \
                 :: "r"(dst), "l"(src))
#define CP_COMMIT() asm volatile("cp.async.commit_group;" ::: "memory")
#define CP_WAIT0()  asm volatile("cp.async.wait_group 0;" ::: "memory")

// ---------------------------------------------------------------------------
// fp32 -> fp16 conversion (8 floats / thread)
// ---------------------------------------------------------------------------
__global__ __launch_bounds__(256) void f2h_kernel(
    const float* __restrict__ in, __half* __restrict__ out, int n)
{
    int i = (blockIdx.x * 256 + threadIdx.x) * 8;
    if (i >= n) return;
    float4 a = *(const float4*)(in + i);
    float4 b = *(const float4*)(in + i + 4);
    uint4 o = { pk_h2(a.x, a.y), pk_h2(a.z, a.w),
                pk_h2(b.x, b.y), pk_h2(b.z, b.w) };
    *(uint4*)(out + i) = o;
}

// ---------------------------------------------------------------------------
// fp16 tensor-core GEMM with cp.async pipelining.
// C[M,N] = A[M,K] @ Bm[N,K]^T; BM=BN=128, BK=32, 256 threads, warp tile 64x32.
// Smem row stride 20 words; double-buffered via cp.async (copy for it+1 in
// flight during it's MMAs). Half or float output.
// ---------------------------------------------------------------------------
#define HSTRIDE 20
#define HROW_BYTES (HSTRIDE * 4)                 // 80
#define HTILE_WORDS (128 * HSTRIDE)              // 2560 u32 per tile
#define HTILE_BYTES (HTILE_WORDS * 4)            // 10240
#define GEMM_SMEM_BYTES (4 * HTILE_BYTES)        // 40960 B

__global__ __launch_bounds__(256) void gemm_nt_h_kernel(
    const __half* __restrict__ A, const __half* __restrict__ Bm,
    __half* __restrict__ Ch, float* __restrict__ Cf, int M, int N, int K)
{
    extern __shared__ uint32_t smw[];
    const uint32_t smBase = smem_u32(smw);

    const int tid  = threadIdx.x;
    const int lane = tid & 31;
    const int warp = tid >> 5;
    const int row0 = blockIdx.y * 128;
    const int col0 = blockIdx.x * 128;
    const int wm   = (warp >> 2) * 64;
    const int wn   = (warp & 3) * 32;
    const int lk   = lane & 3;
    const int lr   = lane >> 2;

    const uint32_t aoff = (uint32_t)(lane & 15) * HROW_BYTES + (uint32_t)(lane >> 4) * 16;
    const uint32_t boff = ((uint32_t)((lane >> 4) * 8 + (lane & 7))) * HROW_BYTES
                        + (uint32_t)((lane >> 3) & 1) * 16;

    // global-load coords: idx -> m = idx>>2, half col = (idx&3)*8
    int mL[2], hcL[2];
    uint32_t stA[2], stB[2];
#pragma unroll
    for (int t = 0; t < 2; t++) {
        int idx = tid + 256 * t;
        mL[t]  = idx >> 2;
        hcL[t] = (idx & 3) << 3;
        uint32_t wb = (uint32_t)(mL[t] * HSTRIDE + ((idx & 3) << 2)) * 4;
        stA[t] = smBase + wb;                          // A tile base (buf 0)
        stB[t] = smBase + 2 * HTILE_BYTES + wb;        // B tile base (buf 0)
    }

    float c[4][4][4];
#pragma unroll
    for (int mi = 0; mi < 4; mi++)
#pragma unroll
        for (int ni = 0; ni < 4; ni++)
#pragma unroll
            for (int r = 0; r < 4; r++) c[mi][ni][r] = 0.f;

    const int niter = K >> 5;

    // prologue: async-copy tile 0 into buf 0
#pragma unroll
    for (int t = 0; t < 2; t++) {
        CP_ASYNC16(stA[t], &A [(size_t)(row0 + mL[t]) * K + hcL[t]]);
        CP_ASYNC16(stB[t], &Bm[(size_t)(col0 + mL[t]) * K + hcL[t]]);
    }
    CP_COMMIT();
    CP_WAIT0();
    __syncthreads();

    for (int it = 0; it < niter; ++it) {
        const int cur = it & 1;
        if (it + 1 < niter) {
            const int k0 = (it + 1) << 5;
            const uint32_t bufo = (uint32_t)((it + 1) & 1) * HTILE_BYTES;
#pragma unroll
            for (int t = 0; t < 2; t++) {
                CP_ASYNC16(stA[t] + bufo, &A [(size_t)(row0 + mL[t]) * K + k0 + hcL[t]]);
                CP_ASYNC16(stB[t] + bufo, &Bm[(size_t)(col0 + mL[t]) * K + k0 + hcL[t]]);
            }
            CP_COMMIT();
        }

        const uint32_t aB = smBase + (uint32_t)cur * HTILE_BYTES + aoff;
        const uint32_t bB = smBase + (uint32_t)(2 + cur) * HTILE_BYTES + boff;
#pragma unroll
        for (int s = 0; s < 2; s++) {
            const uint32_t so = (uint32_t)s * 32;
            uint32_t af[4][4], bf[4][2];
#pragma unroll
            for (int mi = 0; mi < 4; mi++)
                LDSM_X4(af[mi][0], af[mi][1], af[mi][2], af[mi][3],
                        aB + (uint32_t)(wm + 16 * mi) * HROW_BYTES + so);
#pragma unroll
            for (int p = 0; p < 2; p++)
                LDSM_X4(bf[2 * p][0], bf[2 * p][1], bf[2 * p + 1][0], bf[2 * p + 1][1],
                        bB + (uint32_t)(wn + 16 * p) * HROW_BYTES + so);
#pragma unroll
            for (int mi = 0; mi < 4; mi++)
#pragma unroll
                for (int ni = 0; ni < 4; ni++)
                    MMA_F16(c[mi][ni], af[mi], bf[ni]);
        }

        if (it + 1 < niter) CP_WAIT0();
        __syncthreads();
    }

#pragma unroll
    for (int mi = 0; mi < 4; mi++) {
#pragma unroll
        for (int ni = 0; ni < 4; ni++) {
            int r  = row0 + wm + 16 * mi + lr;
            int cc = col0 + wn + 8 * ni + 2 * lk;
            if (Ch) {
                *(uint32_t*)&Ch[(size_t)r * N + cc]       = pk_h2(c[mi][ni][0], c[mi][ni][1]);
                *(uint32_t*)&Ch[(size_t)(r + 8) * N + cc] = pk_h2(c[mi][ni][2], c[mi][ni][3]);
            } else {
                Cf[(size_t)r * N + cc]           = c[mi][ni][0];
                Cf[(size_t)r * N + cc + 1]       = c[mi][ni][1];
                Cf[(size_t)(r + 8) * N + cc]     = c[mi][ni][2];
                Cf[(size_t)(r + 8) * N + cc + 1] = c[mi][ni][3];
            }
        }
    }
}

// ---------------------------------------------------------------------------
// RoPE on half buffers; folds 1/sqrt(HD) scale into Q.
// ---------------------------------------------------------------------------
__global__ __launch_bounds__(256) void rope_h_kernel(
    __half* __restrict__ q, __half* __restrict__ k,
    const float* __restrict__ cosT, const float* __restrict__ sinT)
{
    const int bt  = blockIdx.x;
    const int t   = bt & (T_ - 1);
    const int tid = threadIdx.x;
    const float scale = 0.08838834764831845f;
    const float* cr = cosT + (size_t)t * HD_;
    const float* sr = sinT + (size_t)t * HD_;

    __half* qrow = q + (size_t)bt * D_;
    for (int p = tid; p < H_ * 64; p += 256) {
        int h = p >> 6, i = p & 63;
        __half* base = qrow + h * HD_;
        float q1 = __half2float(base[i]), q2 = __half2float(base[i + 64]);
        base[i]      = __float2half_rn((q1 * cr[i]      - q2 * sr[i]) * scale);
        base[i + 64] = __float2half_rn((q2 * cr[i + 64] + q1 * sr[i + 64]) * scale);
    }
    __half* krow = k + (size_t)bt * KVD_;
    for (int p = tid; p < HKV_ * 64; p += 256) {
        int h = p >> 6, i = p & 63;
        __half* base = krow + h * HD_;
        float k1 = __half2float(base[i]), k2 = __half2float(base[i + 64]);
        base[i]      = __float2half_rn(k1 * cr[i]      - k2 * sr[i]);
        base[i + 64] = __float2half_rn(k2 * cr[i + 64] + k1 * sr[i + 64]);
    }
}

// ---------------------------------------------------------------------------
// fp16 flash attention, cp.async double-buffered K/V.
// Grid: (T/128, H, B). Block: 256 = 8 warps; warp w owns q-rows [w*16,w*16+16).
// Smem (u32 words): two buffers of { Ks[64][68], Vs[64][68] }, 8704 words
// each, at 0 and 8704. Q staging [128][68] aliases buffer 0+1.
// ---------------------------------------------------------------------------
#define AT_BUF_WORDS 8704                 // Ks + Vs per buffer
#define AT_BUF_BYTES (AT_BUF_WORDS * 4)   // 34816
#define AT_VS_WOFF   4352
#define ATTN_SMEM_BYTES (2 * AT_BUF_BYTES)   // 69632
#define KS_ROW_BYTES 272                  // 68 words

__global__ __launch_bounds__(256) void attn_f16_kernel(
    const __half* __restrict__ q, const __half* __restrict__ k,
    const __half* __restrict__ v, __half* __restrict__ o)
{
    extern __shared__ uint32_t sw[];
    uint32_t* Qs = sw;                 // staging [128][68], aliases both buffers

    const int qt  = blockIdx.x;
    const int h   = blockIdx.y;
    const int b   = blockIdx.z;
    const int kvh = h >> 2;
    const int q0  = qt * 128;
    const int tid  = threadIdx.x;
    const int lane = tid & 31;
    const int w    = tid >> 5;
    const int lr   = lane >> 2;
    const int lk   = lane & 3;

    const uint32_t smB = smem_u32(sw);
    const uint32_t brow   = (uint32_t)((lane >> 4) * 8 + (lane & 7));
    const uint32_t bcol16 = (uint32_t)((lane >> 3) & 1) * 16;
    const uint32_t arow   = (uint32_t)(lane & 15);
    const uint32_t asel16 = (uint32_t)(lane >> 4) * 16;

    // per-thread K/V load coords
    const int krow  = tid >> 2;                 // key 0..63
    const int kd0   = (tid & 3) * 32;           // halves
    const uint32_t kvw = (uint32_t)(krow * 68 + (kd0 >> 1)) * 4;  // byte off in buffer

    // ---- stage Q (half, scale pre-folded) and pull A-fragments ----
    {
        int row = tid >> 1;
        int d0  = (tid & 1) * 64;
        const __half* src = q + (size_t)(b * T_ + q0 + row) * D_ + h * HD_ + d0;
#pragma unroll
        for (int j = 0; j < 64; j += 8)
            *(uint4*)&Qs[row * 68 + ((d0 + j) >> 1)] = *(const uint4*)(src + j);
    }
    __syncthreads();

    uint32_t aQ[8][4];
#pragma unroll
    for (int c = 0; c < 8; c++)
        LDSM_X4(aQ[c][0], aQ[c][1], aQ[c][2], aQ[c][3],
                smB + (uint32_t)(w * 16 + arow) * KS_ROW_BYTES
                    + (uint32_t)c * 32 + asel16);
    __syncthreads();

    float O[16][4];
#pragma unroll
    for (int nt = 0; nt < 16; nt++)
#pragma unroll
        for (int r = 0; r < 4; r++) O[nt][r] = 0.f;
    float m0 = -CUDART_INF_F, m1 = -CUDART_INF_F, l0 = 0.f, l1 = 0.f;

    const int row0g = q0 + w * 16 + lr;
    const int nkt = 2 * qt + 2;

    const __half* kbase = k + (size_t)(b * T_) * KVD_ + kvh * HD_ + kd0 + (size_t)krow * KVD_;
    const __half* vbase = v + (size_t)(b * T_) * KVD_ + kvh * HD_ + kd0 + (size_t)krow * KVD_;

    // prologue: async-load tile 0 into buffer 0
#pragma unroll
    for (int j = 0; j < 4; j++) {
        CP_ASYNC16(smB + kvw + 16u * j,                    kbase + 8 * j);
        CP_ASYNC16(smB + AT_VS_WOFF * 4 + kvw + 16u * j,   vbase + 8 * j);
    }
    CP_COMMIT();
    CP_WAIT0();
    __syncthreads();

    for (int kt = 0; kt < nkt; kt++) {
        const uint32_t bufB = smB + (uint32_t)(kt & 1) * AT_BUF_BYTES;

        if (kt + 1 < nkt) {
            const uint32_t nb = smB + (uint32_t)((kt + 1) & 1) * AT_BUF_BYTES;
            const size_t goff = (size_t)(kt + 1) * 64 * KVD_;
#pragma unroll
            for (int j = 0; j < 4; j++) {
                CP_ASYNC16(nb + kvw + 16u * j,                  kbase + goff + 8 * j);
                CP_ASYNC16(nb + AT_VS_WOFF * 4 + kvw + 16u * j, vbase + goff + 8 * j);
            }
            CP_COMMIT();
        }

        const int k0 = kt * 64;
        const bool active = (k0 <= q0 + w * 16 + 15);   // warp-uniform
        if (active) {
            const uint32_t KsB = bufB;
            const uint32_t VsB = bufB + AT_VS_WOFF * 4;

            // ---- S = Q K^T ----
            float s[8][4];
#pragma unroll
            for (int nt = 0; nt < 8; nt++)
#pragma unroll
                for (int r = 0; r < 4; r++) s[nt][r] = 0.f;

#pragma unroll
            for (int c = 0; c < 8; c++) {
                uint32_t bf[8][2];
#pragma unroll
                for (int p = 0; p < 4; p++)
                    LDSM_X4(bf[2 * p][0], bf[2 * p][1], bf[2 * p + 1][0], bf[2 * p + 1][1],
                            KsB + (uint32_t)(p * 16 + brow) * KS_ROW_BYTES
                                + (uint32_t)c * 32 + bcol16);
#pragma unroll
                for (int nt = 0; nt < 8; nt++)
                    MMA_F16(s[nt], aQ[c], bf[nt]);
            }

            // ---- causal mask ----
            if (k0 + 63 > q0 + w * 16) {
#pragma unroll
                for (int nt = 0; nt < 8; nt++) {
                    int c0 = k0 + nt * 8 + 2 * lk;
                    if (c0     > row0g)     s[nt][0] = -CUDART_INF_F;
                    if (c0 + 1 > row0g)     s[nt][1] = -CUDART_INF_F;
                    if (c0     > row0g + 8) s[nt][2] = -CUDART_INF_F;
                    if (c0 + 1 > row0g + 8) s[nt][3] = -CUDART_INF_F;
                }
            }

            // ---- online softmax ----
            float mt0 = -CUDART_INF_F, mt1 = -CUDART_INF_F;
#pragma unroll
            for (int nt = 0; nt < 8; nt++) {
                mt0 = fmaxf(mt0, fmaxf(s[nt][0], s[nt][1]));
                mt1 = fmaxf(mt1, fmaxf(s[nt][2], s[nt][3]));
            }
#pragma unroll
            for (int off = 1; off <= 2; off <<= 1) {
                mt0 = fmaxf(mt0, __shfl_xor_sync(0xffffffffu, mt0, off));
                mt1 = fmaxf(mt1, __shfl_xor_sync(0xffffffffu, mt1, off));
            }
            float mn0 = fmaxf(m0, mt0), mn1 = fmaxf(m1, mt1);
            float al0 = __expf(m0 - mn0), al1 = __expf(m1 - mn1);
            m0 = mn0; m1 = mn1;

            float sum0 = 0.f, sum1 = 0.f;
#pragma unroll
            for (int nt = 0; nt < 8; nt++) {
                s[nt][0] = __expf(s[nt][0] - mn0); sum0 += s[nt][0];
                s[nt][1] = __expf(s[nt][1] - mn0); sum0 += s[nt][1];
                s[nt][2] = __expf(s[nt][2] - mn1); sum1 += s[nt][2];
                s[nt][3] = __expf(s[nt][3] - mn1); sum1 += s[nt][3];
            }
#pragma unroll
            for (int off = 1; off <= 2; off <<= 1) {
                sum0 += __shfl_xor_sync(0xffffffffu, sum0, off);
                sum1 += __shfl_xor_sync(0xffffffffu, sum1, off);
            }
            l0 = l0 * al0 + sum0;
            l1 = l1 * al1 + sum1;
#pragma unroll
            for (int nt = 0; nt < 16; nt++) {
                O[nt][0] *= al0; O[nt][1] *= al0;
                O[nt][2] *= al1; O[nt][3] *= al1;
            }

            // ---- O += P V  (P in registers; V frags via ldmatrix.trans) ----
#pragma unroll
            for (int c = 0; c < 4; c++) {
                uint32_t pa[4];
                pa[0] = pk_h2(s[2 * c][0],     s[2 * c][1]);
                pa[1] = pk_h2(s[2 * c][2],     s[2 * c][3]);
                pa[2] = pk_h2(s[2 * c + 1][0], s[2 * c + 1][1]);
                pa[3] = pk_h2(s[2 * c + 1][2], s[2 * c + 1][3]);
#pragma unroll
                for (int p = 0; p < 8; p++) {
                    uint32_t vb[2][2];
                    LDSM_X4_T(vb[0][0], vb[0][1], vb[1][0], vb[1][1],
                              VsB + (uint32_t)(c * 16 + arow) * KS_ROW_BYTES
                                  + (uint32_t)p * 32 + asel16);
                    MMA_F16(O[2 * p],     pa, vb[0]);
                    MMA_F16(O[2 * p + 1], pa, vb[1]);
                }
            }
        }

        if (kt + 1 < nkt) CP_WAIT0();
        __syncthreads();
    }

    // ---- epilogue (half out) ----
    float inv0 = 1.0f / l0, inv1 = 1.0f / l1;
    size_t r0base = (size_t)(b * T_ + q0 + w * 16 + lr) * D_ + h * HD_;
    size_t r1base = (size_t)(b * T_ + q0 + w * 16 + lr + 8) * D_ + h * HD_;
#pragma unroll
    for (int nt = 0; nt < 16; nt++) {
        *(uint32_t*)&o[r0base + nt * 8 + 2 * lk] = pk_h2(O[nt][0] * inv0, O[nt][1] * inv0);
        *(uint32_t*)&o[r1base + nt * 8 + 2 * lk] = pk_h2(O[nt][2] * inv1, O[nt][3] * inv1);
    }
}

// ---------------------------------------------------------------------------
// Launcher
// ---------------------------------------------------------------------------
extern "C" void kernel_launch(void* const* d_in, const int* in_sizes, int n_in,
                              void* d_out, int out_size)
{
    const float* x    = (const float*)d_in[0];
    const float* cosT = (const float*)d_in[1];
    const float* sinT = (const float*)d_in[2];
    const float* Wq   = (const float*)d_in[3];
    const float* Wk   = (const float*)d_in[4];
    const float* Wv   = (const float*)d_in[5];
    const float* Wo   = (const float*)d_in[6];
    float* out = (float*)d_out;

    __half *xh, *wqh, *wkh, *wvh, *woh, *gq, *gk, *gv, *gattn;
    cudaGetSymbolAddress((void**)&xh,    g_xh);
    cudaGetSymbolAddress((void**)&wqh,   g_wqh);
    cudaGetSymbolAddress((void**)&wkh,   g_wkh);
    cudaGetSymbolAddress((void**)&wvh,   g_wvh);
    cudaGetSymbolAddress((void**)&woh,   g_woh);
    cudaGetSymbolAddress((void**)&gq,    g_q);
    cudaGetSymbolAddress((void**)&gk,    g_k);
    cudaGetSymbolAddress((void**)&gv,    g_v);
    cudaGetSymbolAddress((void**)&gattn, g_attn);

    cudaFuncSetAttribute(attn_f16_kernel, cudaFuncAttributeMaxDynamicSharedMemorySize,
                         ATTN_SMEM_BYTES);
    cudaFuncSetAttribute(gemm_nt_h_kernel,
                         cudaFuncAttributeMaxDynamicSharedMemorySize,
                         GEMM_SMEM_BYTES);

    dim3 blk(256);
    f2h_kernel<<<M_ * D_ / 2048,   blk>>>(x,  xh,  M_ * D_);
    f2h_kernel<<<D_ * D_ / 2048,   blk>>>(Wq, wqh, D_ * D_);
    f2h_kernel<<<KVD_ * D_ / 2048, blk>>>(Wk, wkh, KVD_ * D_);
    f2h_kernel<<<KVD_ * D_ / 2048, blk>>>(Wv, wvh, KVD_ * D_);
    f2h_kernel<<<D_ * D_ / 2048,   blk>>>(Wo, woh, D_ * D_);

    dim3 gq_grid(D_ / 128, M_ / 128);
    dim3 gkv_grid(KVD_ / 128, M_ / 128);

    gemm_nt_h_kernel<<<gq_grid,  blk, GEMM_SMEM_BYTES>>>(xh, wqh, gq, nullptr, M_, D_,   D_);
    gemm_nt_h_kernel<<<gkv_grid, blk, GEMM_SMEM_BYTES>>>(xh, wkh, gk, nullptr, M_, KVD_, D_);
    gemm_nt_h_kernel<<<gkv_grid, blk, GEMM_SMEM_BYTES>>>(xh, wvh, gv, nullptr, M_, KVD_, D_);

    rope_h_kernel<<<M_, blk>>>(gq, gk, cosT, sinT);

    dim3 ga(T_ / 128, H_, B_);
    attn_f16_kernel<<<ga, blk, ATTN_SMEM_BYTES>>>(gq, gk, gv, gattn);

    gemm_nt_h_kernel<<<gq_grid, blk, GEMM_SMEM_BYTES>>>(gattn, woh, nullptr, out, M_, D_, D_);
}